// round 11
// baseline (speedup 1.0000x reference)
#include <cuda_runtime.h>
#include <math.h>

// ---------------- problem constants ----------------
#define Bn 2
#define Ln 2048
#define Dn 512
#define En 768
#define EPSV 1e-6f

// ---------------- scratch (device globals; no allocation) ----------------
__device__ __align__(16) float g_q[Bn * Ln * Dn];      // 8 MB
__device__ __align__(16) float g_k[Bn * Ln * Dn];      // 8 MB
__device__ __align__(16) float g_G[6 * Dn * Dn];       // 6 MB  [Gkk0,Gkk1,Gkq0,Gkq1,Gqq0,Gqq1]
__device__ __align__(16) float g_T[6 * Ln * Dn];       // 24 MB [Tc0,Tc1,Tf0,Tf1,Ts0,Ts1]
__device__ __align__(16) float g_cs[4 * Ln];           // col scales [C b0, C b1, S b0, S b1]

// ---------------- generic batched fp32 GEMM, 128x128x8 tiles ----------------
// C[M,N] = op(A) * op(B);  TA: A stored [K,M], else [M,K];  TB: B stored [N,K], else [K,N].
// All of M, N multiples of 128 (via grid); K multiple of 8. Row-major, leading dims given.
struct GB { const float* A[6]; const float* B[6]; float* C[6]; };

template<bool TA, bool TB>
__global__ __launch_bounds__(256)
void gemm128(GB gb, int K, int lda, int ldb, int ldc)
{
    __shared__ float As[8][128];
    __shared__ float Bs[8][128];
    const float* __restrict__ A  = gb.A[blockIdx.z];
    const float* __restrict__ Bm = gb.B[blockIdx.z];
    float* __restrict__ C        = gb.C[blockIdx.z];

    const int tid = threadIdx.x;
    const int m0 = blockIdx.y * 128, n0 = blockIdx.x * 128;
    const int tx = tid & 15, ty = tid >> 4;

    float acc[8][8] = {};

    int ar, ac, br, bc;
    if (!TA) { ar = tid >> 1; ac = (tid & 1) * 4; }   // A[m0+ar][k0+ac..+3]
    else     { ar = tid >> 5; ac = (tid & 31) * 4; }  // A[k0+ar][m0+ac..+3]
    if (!TB) { br = tid >> 5; bc = (tid & 31) * 4; }  // B[k0+br][n0+bc..+3]
    else     { br = tid >> 1; bc = (tid & 1) * 4; }   // B[n0+br][k0+bc..+3]

    for (int k0 = 0; k0 < K; k0 += 8) {
        __syncthreads();
        float4 ra = TA ? *(const float4*)(A + (size_t)(k0 + ar) * lda + m0 + ac)
                       : *(const float4*)(A + (size_t)(m0 + ar) * lda + k0 + ac);
        float4 rb = TB ? *(const float4*)(Bm + (size_t)(n0 + br) * ldb + k0 + bc)
                       : *(const float4*)(Bm + (size_t)(k0 + br) * ldb + n0 + bc);
        if (TA) { *(float4*)&As[ar][ac] = ra; }
        else { As[ac+0][ar]=ra.x; As[ac+1][ar]=ra.y; As[ac+2][ar]=ra.z; As[ac+3][ar]=ra.w; }
        if (!TB) { *(float4*)&Bs[br][bc] = rb; }
        else { Bs[bc+0][br]=rb.x; Bs[bc+1][br]=rb.y; Bs[bc+2][br]=rb.z; Bs[bc+3][br]=rb.w; }
        __syncthreads();
#pragma unroll
        for (int kk = 0; kk < 8; kk++) {
            float4 a0 = *(float4*)&As[kk][ty * 4];
            float4 a1 = *(float4*)&As[kk][64 + ty * 4];
            float4 b0 = *(float4*)&Bs[kk][tx * 4];
            float4 b1 = *(float4*)&Bs[kk][64 + tx * 4];
            float av[8] = {a0.x, a0.y, a0.z, a0.w, a1.x, a1.y, a1.z, a1.w};
            float bv[8] = {b0.x, b0.y, b0.z, b0.w, b1.x, b1.y, b1.z, b1.w};
#pragma unroll
            for (int i = 0; i < 8; i++)
#pragma unroll
                for (int j = 0; j < 8; j++)
                    acc[i][j] = fmaf(av[i], bv[j], acc[i][j]);
        }
    }

#pragma unroll
    for (int i = 0; i < 8; i++) {
        int r = m0 + ((i < 4) ? (ty * 4 + i) : (64 + ty * 4 + i - 4));
        *(float4*)&C[(size_t)r * ldc + n0 + tx * 4] =
            make_float4(acc[i][0], acc[i][1], acc[i][2], acc[i][3]);
        *(float4*)&C[(size_t)r * ldc + n0 + 64 + tx * 4] =
            make_float4(acc[i][4], acc[i][5], acc[i][6], acc[i][7]);
    }
}

// ---------------- reductions (256-thread blocks, sm = 16 floats) -----------
__device__ __forceinline__ float warp_sum_f(float v) {
#pragma unroll
    for (int o = 16; o; o >>= 1) v += __shfl_xor_sync(0xffffffffu, v, o);
    return v;
}
__device__ __forceinline__ float blk_sum_256(float v, float* sm) {
    v = warp_sum_f(v);
    int w = threadIdx.x >> 5, l = threadIdx.x & 31;
    __syncthreads();
    if (l == 0) sm[w] = v;
    __syncthreads();
    float r = 0.f;
#pragma unroll
    for (int i = 0; i < 8; i++) r += sm[i];
    return r;
}
__device__ __forceinline__ float blk_max_256(float v, float* sm) {
#pragma unroll
    for (int o = 16; o; o >>= 1) v = fmaxf(v, __shfl_xor_sync(0xffffffffu, v, o));
    int w = threadIdx.x >> 5, l = threadIdx.x & 31;
    __syncthreads();
    if (l == 0) sm[w] = v;
    __syncthreads();
    float r = sm[0];
#pragma unroll
    for (int i = 1; i < 8; i++) r = fmaxf(r, sm[i]);
    return r;
}
__device__ __forceinline__ float2 blk_sum2_256(float2 v, float* sm) {
#pragma unroll
    for (int o = 16; o; o >>= 1) {
        v.x += __shfl_xor_sync(0xffffffffu, v.x, o);
        v.y += __shfl_xor_sync(0xffffffffu, v.y, o);
    }
    int w = threadIdx.x >> 5, l = threadIdx.x & 31;
    __syncthreads();
    if (l == 0) { sm[w] = v.x; sm[8 + w] = v.y; }
    __syncthreads();
    float2 r = make_float2(0.f, 0.f);
#pragma unroll
    for (int i = 0; i < 8; i++) { r.x += sm[i]; r.y += sm[8 + i]; }
    return r;
}

// Newton solve for the 1.5-entmax threshold: sum(max(z - tau, 0)^2) = 1.
// z must already be halved and max-subtracted (so max(z) == 0, tau* in [-1, 0)).
// f is convex decreasing; Newton from tau=-1 converges monotonically from the left.
__device__ float entmax_tau_256(const float z[8], float* sm) {
    float tau = -1.0f;
#pragma unroll 1
    for (int it = 0; it < 50; it++) {
        float2 s = make_float2(0.f, 0.f);
#pragma unroll
        for (int j = 0; j < 8; j++) {
            float d = fmaxf(z[j] - tau, 0.f);
            s.x += d; s.y += d * d;
        }
        s = blk_sum2_256(s, sm);     // uniform across block
        if (s.x <= 0.f) break;
        float dt = (s.y - 1.0f) / (2.0f * s.x);
        tau += dt;
        if (dt <= 1e-8f) break;      // uniform predicate (block-reduced values)
    }
    return tau;
}

// ---------------- LayerNorm + RoPE (in place on g_q / g_k) ----------------
__global__ __launch_bounds__(128)
void lnrope_kernel(float* __restrict__ q, float* __restrict__ k,
                   const float* __restrict__ qg, const float* __restrict__ qb,
                   const float* __restrict__ kg, const float* __restrict__ kb)
{
    __shared__ float sred[4];
    int row = blockIdx.x;             // 0 .. Bn*Ln-1
    int t = row & (Ln - 1);           // sequence position
    float* base = (blockIdx.y ? k : q) + (size_t)row * Dn;
    const float* gamma = blockIdx.y ? kg : qg;
    const float* beta  = blockIdx.y ? kb : qb;
    int tid = threadIdx.x;

    float v0 = base[tid], v1 = base[tid + 128], v2 = base[tid + 256], v3 = base[tid + 384];
    float s = warp_sum_f(v0 + v1 + v2 + v3);
    if ((tid & 31) == 0) sred[tid >> 5] = s;
    __syncthreads();
    float mu = (sred[0] + sred[1] + sred[2] + sred[3]) * (1.0f / 512.0f);
    float d0 = v0 - mu, d1 = v1 - mu, d2 = v2 - mu, d3 = v3 - mu;
    float sq = warp_sum_f(d0*d0 + d1*d1 + d2*d2 + d3*d3);
    __syncthreads();
    if ((tid & 31) == 0) sred[tid >> 5] = sq;
    __syncthreads();
    float var = (sred[0] + sred[1] + sred[2] + sred[3]) * (1.0f / 512.0f);
    float rs = rsqrtf(var + 1e-5f);

    float n0 = d0 * rs * gamma[tid]       + beta[tid];
    float n1 = d1 * rs * gamma[tid + 128] + beta[tid + 128];
    float n2 = d2 * rs * gamma[tid + 256] + beta[tid + 256];
    float n3 = d3 * rs * gamma[tid + 384] + beta[tid + 384];

    // RoPE pairs (d, d+256), d in [0,256). inv_freq in fp64 -> correctly-rounded fp32.
    const double lg = 9.210340371976184 / 256.0;   // log(10000)/256
    float inv0 = (float)exp(-(double)tid * lg);
    float inv1 = (float)exp(-(double)(tid + 128) * lg);
    float ft = (float)t;
    float a0 = ft * inv0, a1 = ft * inv1;
    float c0 = cosf(a0), s0 = sinf(a0);
    float c1 = cosf(a1), s1 = sinf(a1);
    base[tid]       = n0 * c0 - n2 * s0;
    base[tid + 256] = n2 * c0 + n0 * s0;
    base[tid + 128] = n1 * c1 - n3 * s1;
    base[tid + 384] = n3 * c1 + n1 * s1;
}

// ------- row-center + scale + entmax + clip (in place on out slots 1..3) ---
__global__ __launch_bounds__(256)
void entmax_p_kernel(float* __restrict__ out,
                     const float* __restrict__ Cw, const float* __restrict__ Fw,
                     const float* __restrict__ Sw)
{
    __shared__ float sm[16];
    int row = blockIdx.x, b = blockIdx.y, mat = blockIdx.z, tid = threadIdx.x;
    size_t LL = (size_t)Ln * Ln;
    float* base = out + ((size_t)((mat + 1) * Bn + b)) * LL + (size_t)row * Ln;
    const float* wp = (mat == 0) ? Cw : (mat == 1 ? Fw : Sw);
    float w = 2.0f / (1.0f + expf(-wp[0]));

    float z[8];
#pragma unroll
    for (int j = 0; j < 8; j++) z[j] = base[tid + 256 * j];

    float s = 0.f;
#pragma unroll
    for (int j = 0; j < 8; j++) s += z[j];
    s = blk_sum_256(s, sm);
    float mu = s * (1.0f / 2048.0f);

    float hw = 0.5f * w;
    float m = -3.4e38f;
#pragma unroll
    for (int j = 0; j < 8; j++) { z[j] = (z[j] - mu) * hw; m = fmaxf(m, z[j]); }
    m = blk_max_256(m, sm);
#pragma unroll
    for (int j = 0; j < 8; j++) z[j] -= m;

    float tau = entmax_tau_256(z, sm);
#pragma unroll
    for (int j = 0; j < 8; j++) {
        float d = fmaxf(z[j] - tau, 0.f);
        base[tid + 256 * j] = fminf(d * d, 1.0f - EPSV);   // clip(., 0, 1-EPS)
    }
}

// ---------------- column rsqrt scales for pC / pS ----------------
__global__ __launch_bounds__(256)
void colsum_kernel(const float* __restrict__ out)
{
    int j = blockIdx.x * 256 + threadIdx.x;
    int b = blockIdx.y;
    int m = blockIdx.z;   // 0 -> pC (slot 1), 1 -> pS (slot 3)
    size_t LL = (size_t)Ln * Ln;
    const float* base = out + ((size_t)((m ? 3 : 1) * Bn + b)) * LL + j;
    float s = 0.f;
    for (int i = 0; i < Ln; i++) s += base[(size_t)i * Ln];
    g_cs[(m * Bn + b) * Ln + j] = rsqrtf(s + EPSV);
}

// ----- fused: col-scale + EPS affine + log-combine + diag mask + entmax(H) --
__global__ __launch_bounds__(256)
void finalize_kernel(float* __restrict__ out)
{
    __shared__ float sm[16];
    int row = blockIdx.x, b = blockIdx.y, tid = threadIdx.x;
    size_t LL = (size_t)Ln * Ln;
    float* pH = out + ((size_t)(0 * Bn + b)) * LL + (size_t)row * Ln;
    float* pC = out + ((size_t)(1 * Bn + b)) * LL + (size_t)row * Ln;
    float* pF = out + ((size_t)(2 * Bn + b)) * LL + (size_t)row * Ln;
    float* pS = out + ((size_t)(3 * Bn + b)) * LL + (size_t)row * Ln;
    const float Aa = 1.0f - 2.0f * EPSV;

    float h[8];
#pragma unroll
    for (int m = 0; m < 8; m++) {
        int j = tid + 256 * m;
        float csC = g_cs[(0 * Bn + b) * Ln + j];
        float csS = g_cs[(1 * Bn + b) * Ln + j];
        float c = fmaf(pC[j] * csC, Aa, EPSV);   // >= EPS automatically (p >= 0)
        float f = fmaf(pF[j],       Aa, EPSV);
        float s = fmaf(pS[j] * csS, Aa, EPSV);
        pC[j] = c; pF[j] = f; pS[j] = s;
        float hh = (logf(c) + logf(f) + logf(s)) * (1.0f / 3.0f);
        h[m] = (j == row) ? -1e9f : hh;
    }

    // entmax15 over the h row
    float m = -3.4e38f;
#pragma unroll
    for (int j = 0; j < 8; j++) { h[j] *= 0.5f; m = fmaxf(m, h[j]); }
    m = blk_max_256(m, sm);
#pragma unroll
    for (int j = 0; j < 8; j++) h[j] -= m;
    float tau = entmax_tau_256(h, sm);
#pragma unroll
    for (int j = 0; j < 8; j++) {
        float d = fmaxf(h[j] - tau, 0.f);
        pH[tid + 256 * j] = d * d;
    }
}

// ---------------- launch ----------------
extern "C" void kernel_launch(void* const* d_in, const int* in_sizes, int n_in,
                              void* d_out, int out_size)
{
    const float* x  = (const float*)d_in[0];   // [2,2048,768]
    const float* Wq = (const float*)d_in[1];   // [512,768]
    const float* Wk = (const float*)d_in[2];   // [512,768]
    const float* qg = (const float*)d_in[3];
    const float* qb = (const float*)d_in[4];
    const float* kg = (const float*)d_in[5];
    const float* kb = (const float*)d_in[6];
    const float* Cw = (const float*)d_in[7];
    const float* Fw = (const float*)d_in[8];
    const float* Sw = (const float*)d_in[9];
    float* out = (float*)d_out;                // [H, pC, pF, pS] each [2,2048,2048]

    float *q, *k, *G, *T;
    cudaGetSymbolAddress((void**)&q, g_q);
    cudaGetSymbolAddress((void**)&k, g_k);
    cudaGetSymbolAddress((void**)&G, g_G);
    cudaGetSymbolAddress((void**)&T, g_T);

    const size_t LL = (size_t)Ln * Ln, LD = (size_t)Ln * Dn, DD = (size_t)Dn * Dn;

    // 1) projections: q_pre = x @ Wq^T, k_pre = x @ Wk^T   (M=4096, N=512, K=768)
    {
        GB gb{};
        gb.A[0] = x; gb.B[0] = Wq; gb.C[0] = q;
        gb.A[1] = x; gb.B[1] = Wk; gb.C[1] = k;
        gemm128<false, true><<<dim3(Dn / 128, (Bn * Ln) / 128, 2), 256>>>(gb, En, En, En, Dn);
    }

    // 2) LayerNorm + RoPE in place
    lnrope_kernel<<<dim3(Bn * Ln, 2), 128>>>(q, k, qg, qb, kg, kb);

    // 3) Gram matrices: G[d][e] = sum_l A[l,d] B[l,e]   (M=N=512, K=2048, TA)
    {
        GB gb{};
        for (int b = 0; b < 2; b++) {
            gb.A[0 + b] = k + b * LD; gb.B[0 + b] = k + b * LD; gb.C[0 + b] = G + (0 + b) * DD; // Gkk
            gb.A[2 + b] = k + b * LD; gb.B[2 + b] = q + b * LD; gb.C[2 + b] = G + (2 + b) * DD; // Gkq
            gb.A[4 + b] = q + b * LD; gb.B[4 + b] = q + b * LD; gb.C[4 + b] = G + (4 + b) * DD; // Gqq
        }
        gemm128<true, false><<<dim3(Dn / 128, Dn / 128, 6), 256>>>(gb, Ln, Dn, Dn, Dn);
    }

    // 4) T = U @ G   (M=2048, N=512, K=512)
    {
        GB gb{};
        for (int b = 0; b < 2; b++) {
            gb.A[0 + b] = q + b * LD; gb.B[0 + b] = G + (0 + b) * DD; gb.C[0 + b] = T + (0 + b) * LD; // Tc
            gb.A[2 + b] = q + b * LD; gb.B[2 + b] = G + (2 + b) * DD; gb.C[2 + b] = T + (2 + b) * LD; // Tf
            gb.A[4 + b] = k + b * LD; gb.B[4 + b] = G + (4 + b) * DD; gb.C[4 + b] = T + (4 + b) * LD; // Ts
        }
        gemm128<false, false><<<dim3(Dn / 128, Ln / 128, 6), 256>>>(gb, Dn, Dn, Dn, Dn);
    }

    // 5) raw = T @ V^T  -> out slots 1..3   (M=N=2048, K=512, TB)
    {
        GB gb{};
        for (int b = 0; b < 2; b++) {
            gb.A[0 + b] = T + (0 + b) * LD; gb.B[0 + b] = q + b * LD; gb.C[0 + b] = out + (size_t)(1 * Bn + b) * LL; // C_raw
            gb.A[2 + b] = T + (2 + b) * LD; gb.B[2 + b] = k + b * LD; gb.C[2 + b] = out + (size_t)(2 * Bn + b) * LL; // F_raw
            gb.A[4 + b] = T + (4 + b) * LD; gb.B[4 + b] = k + b * LD; gb.C[4 + b] = out + (size_t)(3 * Bn + b) * LL; // S_raw
        }
        gemm128<false, true><<<dim3(Ln / 128, Ln / 128, 6), 256>>>(gb, Dn, Dn, Dn, Ln);
    }

    // 6) entmax over raw rows (in place), 7) column scales, 8) finalize + H
    entmax_p_kernel<<<dim3(Ln, Bn, 3), 256>>>(out, Cw, Fw, Sw);
    colsum_kernel<<<dim3(Ln / 256, Bn, 2), 256>>>(out);
    finalize_kernel<<<dim3(Ln, Bn), 256>>>(out);
}

// round 13
// speedup vs baseline: 1.1053x; 1.1053x over previous
#include <cuda_runtime.h>
#include <math.h>
#include <stdint.h>

// ---------------- problem constants ----------------
#define Bn 2
#define Ln 2048
#define Dn 512
#define En 768
#define EPSV 1e-6f

// ---------------- scratch (device globals; no allocation) ----------------
__device__ __align__(16) float g_q[Bn * Ln * Dn];      // 8 MB
__device__ __align__(16) float g_k[Bn * Ln * Dn];      // 8 MB
__device__ __align__(16) float g_G[6 * Dn * Dn];       // 6 MB  [Gkk0,Gkk1,Gkq0,Gkq1,Gqq0,Gqq1]
__device__ __align__(16) float g_T[6 * Ln * Dn];       // 24 MB [Tc0,Tc1,Tf0,Tf1,Ts0,Ts1]
__device__ __align__(16) float g_cs[4 * Ln];           // col scales [C b0, C b1, S b0, S b1]
__device__ __align__(16) float g_csp[4 * 8 * Ln];      // colsum partials

// ---------------- tf32 helpers ----------------
__device__ __forceinline__ float tf32r(float x) {
    uint32_t u;
    asm("cvt.rna.tf32.f32 %0, %1;" : "=r"(u) : "f"(x));
    return __uint_as_float(u);
}
__device__ __forceinline__ void mma_tf32(float* c, const uint32_t* a, const uint32_t* b) {
    asm volatile(
        "mma.sync.aligned.m16n8k8.row.col.f32.tf32.tf32.f32 "
        "{%0,%1,%2,%3}, {%4,%5,%6,%7}, {%8,%9}, {%0,%1,%2,%3};"
        : "+f"(c[0]), "+f"(c[1]), "+f"(c[2]), "+f"(c[3])
        : "r"(a[0]), "r"(a[1]), "r"(a[2]), "r"(a[3]), "r"(b[0]), "r"(b[1]));
}

// ------- batched 3xTF32 tensor-core GEMM, 128x128x16 tiles, fp32-grade -----
// C[M,N] = op(A)*op(B); TA: A stored [K,M] else [M,K]; TB: B stored [N,K] else [K,N].
// M,N multiples of 128 (grid); K multiple of 16. Each operand split hi/lo
// (hi = tf32(x), lo = tf32(x - hi)); acc += Alo*Bhi + Ahi*Blo + Ahi*Bhi.
// Effective precision ~2^-22 relative (better than fp32 FMA chain).
// smem semantic: tile[k][m] at physical column m ^ ((k&3)<<3) (conflict-free).
// Dynamic smem: 4 arrays x [2][16][128] floats = 64 KB.
struct GB { const float* A[6]; const float* B[6]; float* C[6]; };

#define SMBUF 2048   // floats per [16][128] slice

template<bool TA, bool TB>
__global__ __launch_bounds__(256)
void mma128(GB gb, int K, int lda, int ldb, int ldc)
{
    extern __shared__ float sm4[];
    float* AsH = sm4;            // [2][16][128]
    float* AsL = sm4 + 2 * SMBUF;
    float* BsH = sm4 + 4 * SMBUF;
    float* BsL = sm4 + 6 * SMBUF;

    const float* __restrict__ A  = gb.A[blockIdx.z];
    const float* __restrict__ Bm = gb.B[blockIdx.z];
    float* __restrict__ C        = gb.C[blockIdx.z];

    const int tid = threadIdx.x, lane = tid & 31, warp = tid >> 5;
    const int wm = (warp >> 2) * 64, wn = (warp & 3) * 32;   // warp tile 64x32
    const int m0 = blockIdx.y * 128, n0 = blockIdx.x * 128;

    float acc[4][4][4];
#pragma unroll
    for (int i = 0; i < 4; i++)
#pragma unroll
        for (int j = 0; j < 4; j++)
#pragma unroll
            for (int v = 0; v < 4; v++) acc[i][j][v] = 0.f;

    float4 ra[2], rb[2];

    auto ldgA = [&](int k0) {
        if (!TA) {
            int m = tid & 127, kq0 = tid >> 7;               // kq0 in {0,1}
#pragma unroll
            for (int p = 0; p < 2; p++) {
                int kq = kq0 + p * 2;                        // 0..3
                ra[p] = *(const float4*)(A + (size_t)(m0 + m) * lda + k0 + kq * 4);
            }
        } else {
#pragma unroll
            for (int p = 0; p < 2; p++) {
                int qi = tid + p * 256;
                int k = qi >> 5, m = (qi & 31) * 4;
                ra[p] = *(const float4*)(A + (size_t)(k0 + k) * lda + m0 + m);
            }
        }
    };
    auto ldgB = [&](int k0) {
        if (!TB) {
#pragma unroll
            for (int p = 0; p < 2; p++) {
                int qi = tid + p * 256;
                int k = qi >> 5, n = (qi & 31) * 4;
                rb[p] = *(const float4*)(Bm + (size_t)(k0 + k) * ldb + n0 + n);
            }
        } else {
            int n = tid & 127, kq0 = tid >> 7;
#pragma unroll
            for (int p = 0; p < 2; p++) {
                int kq = kq0 + p * 2;
                rb[p] = *(const float4*)(Bm + (size_t)(n0 + n) * ldb + k0 + kq * 4);
            }
        }
    };
    auto stsA = [&](int buf) {
        int base = buf * SMBUF;
        if (!TA) {
            int m = tid & 127, kq0 = tid >> 7;
#pragma unroll
            for (int p = 0; p < 2; p++) {
                int k = (kq0 + p * 2) * 4;
                float v[4] = {ra[p].x, ra[p].y, ra[p].z, ra[p].w};
#pragma unroll
                for (int j = 0; j < 4; j++) {
                    float hi = tf32r(v[j]);
                    int idx = base + (k + j) * 128 + (m ^ (j << 3));
                    AsH[idx] = hi;
                    AsL[idx] = tf32r(v[j] - hi);
                }
            }
        } else {
#pragma unroll
            for (int p = 0; p < 2; p++) {
                int qi = tid + p * 256;
                int k = qi >> 5, m = (qi & 31) * 4;
                float4 h = make_float4(tf32r(ra[p].x), tf32r(ra[p].y),
                                       tf32r(ra[p].z), tf32r(ra[p].w));
                float4 l = make_float4(tf32r(ra[p].x - h.x), tf32r(ra[p].y - h.y),
                                       tf32r(ra[p].z - h.z), tf32r(ra[p].w - h.w));
                int idx = base + k * 128 + (m ^ ((k & 3) << 3));
                *(float4*)&AsH[idx] = h;
                *(float4*)&AsL[idx] = l;
            }
        }
    };
    auto stsB = [&](int buf) {
        int base = buf * SMBUF;
        if (!TB) {
#pragma unroll
            for (int p = 0; p < 2; p++) {
                int qi = tid + p * 256;
                int k = qi >> 5, n = (qi & 31) * 4;
                float4 h = make_float4(tf32r(rb[p].x), tf32r(rb[p].y),
                                       tf32r(rb[p].z), tf32r(rb[p].w));
                float4 l = make_float4(tf32r(rb[p].x - h.x), tf32r(rb[p].y - h.y),
                                       tf32r(rb[p].z - h.z), tf32r(rb[p].w - h.w));
                int idx = base + k * 128 + (n ^ ((k & 3) << 3));
                *(float4*)&BsH[idx] = h;
                *(float4*)&BsL[idx] = l;
            }
        } else {
            int n = tid & 127, kq0 = tid >> 7;
#pragma unroll
            for (int p = 0; p < 2; p++) {
                int k = (kq0 + p * 2) * 4;
                float v[4] = {rb[p].x, rb[p].y, rb[p].z, rb[p].w};
#pragma unroll
                for (int j = 0; j < 4; j++) {
                    float hi = tf32r(v[j]);
                    int idx = base + (k + j) * 128 + (n ^ (j << 3));
                    BsH[idx] = hi;
                    BsL[idx] = tf32r(v[j] - hi);
                }
            }
        }
    };
    auto compute = [&](int buf) {
        const int base = buf * SMBUF;
        const int sw = (lane & 3) << 3;
#pragma unroll
        for (int kc = 0; kc < 2; kc++) {
            int c = kc * 8 + (lane & 3);
            int rowc0 = base + c * 128, rowc4 = base + (c + 4) * 128;
            uint32_t afh[4][4], afl[4][4];
#pragma unroll
            for (int i = 0; i < 4; i++) {
                int r = wm + i * 16 + (lane >> 2);
                int i00 = rowc0 + (r ^ sw), i01 = rowc0 + ((r + 8) ^ sw);
                int i10 = rowc4 + (r ^ sw), i11 = rowc4 + ((r + 8) ^ sw);
                afh[i][0] = __float_as_uint(AsH[i00]);
                afh[i][1] = __float_as_uint(AsH[i01]);
                afh[i][2] = __float_as_uint(AsH[i10]);
                afh[i][3] = __float_as_uint(AsH[i11]);
                afl[i][0] = __float_as_uint(AsL[i00]);
                afl[i][1] = __float_as_uint(AsL[i01]);
                afl[i][2] = __float_as_uint(AsL[i10]);
                afl[i][3] = __float_as_uint(AsL[i11]);
            }
#pragma unroll
            for (int j = 0; j < 4; j++) {
                int n = wn + j * 8 + (lane >> 2);
                uint32_t bh[2], bl[2];
                bh[0] = __float_as_uint(BsH[rowc0 + (n ^ sw)]);
                bh[1] = __float_as_uint(BsH[rowc4 + (n ^ sw)]);
                bl[0] = __float_as_uint(BsL[rowc0 + (n ^ sw)]);
                bl[1] = __float_as_uint(BsL[rowc4 + (n ^ sw)]);
#pragma unroll
                for (int i = 0; i < 4; i++) {
                    mma_tf32(acc[i][j], afl[i], bh);   // small terms first
                    mma_tf32(acc[i][j], afh[i], bl);
                    mma_tf32(acc[i][j], afh[i], bh);
                }
            }
        }
    };

    const int nt = K >> 4;
    ldgA(0); ldgB(0); stsA(0); stsB(0);
    __syncthreads();
#pragma unroll 1
    for (int t = 0; t < nt; t++) {
        int buf = t & 1;
        if (t + 1 < nt) { ldgA((t + 1) << 4); ldgB((t + 1) << 4); }
        compute(buf);
        if (t + 1 < nt) { stsA(buf ^ 1); stsB(buf ^ 1); __syncthreads(); }
    }

#pragma unroll
    for (int i = 0; i < 4; i++) {
        int r = m0 + wm + i * 16 + (lane >> 2);
#pragma unroll
        for (int j = 0; j < 4; j++) {
            int cN = n0 + wn + j * 8 + (lane & 3) * 2;
            *(float2*)&C[(size_t)r * ldc + cN]       = make_float2(acc[i][j][0], acc[i][j][1]);
            *(float2*)&C[(size_t)(r + 8) * ldc + cN] = make_float2(acc[i][j][2], acc[i][j][3]);
        }
    }
}

// ---------------- reductions (256-thread blocks, sm = 16 floats) -----------
__device__ __forceinline__ float warp_sum_f(float v) {
#pragma unroll
    for (int o = 16; o; o >>= 1) v += __shfl_xor_sync(0xffffffffu, v, o);
    return v;
}
__device__ __forceinline__ float blk_sum_256(float v, float* sm) {
    v = warp_sum_f(v);
    int w = threadIdx.x >> 5, l = threadIdx.x & 31;
    __syncthreads();
    if (l == 0) sm[w] = v;
    __syncthreads();
    float r = 0.f;
#pragma unroll
    for (int i = 0; i < 8; i++) r += sm[i];
    return r;
}
__device__ __forceinline__ float blk_max_256(float v, float* sm) {
#pragma unroll
    for (int o = 16; o; o >>= 1) v = fmaxf(v, __shfl_xor_sync(0xffffffffu, v, o));
    int w = threadIdx.x >> 5, l = threadIdx.x & 31;
    __syncthreads();
    if (l == 0) sm[w] = v;
    __syncthreads();
    float r = sm[0];
#pragma unroll
    for (int i = 1; i < 8; i++) r = fmaxf(r, sm[i]);
    return r;
}
__device__ __forceinline__ float2 blk_sum2_256(float2 v, float* sm) {
#pragma unroll
    for (int o = 16; o; o >>= 1) {
        v.x += __shfl_xor_sync(0xffffffffu, v.x, o);
        v.y += __shfl_xor_sync(0xffffffffu, v.y, o);
    }
    int w = threadIdx.x >> 5, l = threadIdx.x & 31;
    __syncthreads();
    if (l == 0) { sm[w] = v.x; sm[8 + w] = v.y; }
    __syncthreads();
    float2 r = make_float2(0.f, 0.f);
#pragma unroll
    for (int i = 0; i < 8; i++) { r.x += sm[i]; r.y += sm[8 + i]; }
    return r;
}

// Newton solve for 1.5-entmax threshold: sum(max(z - tau, 0)^2) = 1.
// z halved and max-subtracted (max(z) == 0, tau* in [-1, 0)). Convex decreasing;
// Newton from tau=-1 converges monotonically from the left.
__device__ float entmax_tau_256(const float z[8], float* sm) {
    float tau = -1.0f;
#pragma unroll 1
    for (int it = 0; it < 50; it++) {
        float2 s = make_float2(0.f, 0.f);
#pragma unroll
        for (int j = 0; j < 8; j++) {
            float d = fmaxf(z[j] - tau, 0.f);
            s.x += d; s.y += d * d;
        }
        s = blk_sum2_256(s, sm);
        if (s.x <= 0.f) break;
        float dt = (s.y - 1.0f) / (2.0f * s.x);
        tau += dt;
        if (dt <= 1e-8f) break;
    }
    return tau;
}

// ---------------- LayerNorm + RoPE (in place on g_q / g_k) ----------------
__global__ __launch_bounds__(128)
void lnrope_kernel(float* __restrict__ q, float* __restrict__ k,
                   const float* __restrict__ qg, const float* __restrict__ qb,
                   const float* __restrict__ kg, const float* __restrict__ kb)
{
    __shared__ float sred[4];
    int row = blockIdx.x;
    int t = row & (Ln - 1);
    float* base = (blockIdx.y ? k : q) + (size_t)row * Dn;
    const float* gamma = blockIdx.y ? kg : qg;
    const float* beta  = blockIdx.y ? kb : qb;
    int tid = threadIdx.x;

    float v0 = base[tid], v1 = base[tid + 128], v2 = base[tid + 256], v3 = base[tid + 384];
    float s = warp_sum_f(v0 + v1 + v2 + v3);
    if ((tid & 31) == 0) sred[tid >> 5] = s;
    __syncthreads();
    float mu = (sred[0] + sred[1] + sred[2] + sred[3]) * (1.0f / 512.0f);
    float d0 = v0 - mu, d1 = v1 - mu, d2 = v2 - mu, d3 = v3 - mu;
    float sq = warp_sum_f(d0*d0 + d1*d1 + d2*d2 + d3*d3);
    __syncthreads();
    if ((tid & 31) == 0) sred[tid >> 5] = sq;
    __syncthreads();
    float var = (sred[0] + sred[1] + sred[2] + sred[3]) * (1.0f / 512.0f);
    float rs = rsqrtf(var + 1e-5f);

    float n0 = d0 * rs * gamma[tid]       + beta[tid];
    float n1 = d1 * rs * gamma[tid + 128] + beta[tid + 128];
    float n2 = d2 * rs * gamma[tid + 256] + beta[tid + 256];
    float n3 = d3 * rs * gamma[tid + 384] + beta[tid + 384];

    const double lg = 9.210340371976184 / 256.0;   // log(10000)/256
    float inv0 = (float)exp(-(double)tid * lg);
    float inv1 = (float)exp(-(double)(tid + 128) * lg);
    float ft = (float)t;
    float a0 = ft * inv0, a1 = ft * inv1;
    float c0 = cosf(a0), s0 = sinf(a0);
    float c1 = cosf(a1), s1 = sinf(a1);
    base[tid]       = n0 * c0 - n2 * s0;
    base[tid + 256] = n2 * c0 + n0 * s0;
    base[tid + 128] = n1 * c1 - n3 * s1;
    base[tid + 384] = n3 * c1 + n1 * s1;
}

// ------- row-center + scale + entmax + clip (in place on out slots 1..3) ---
__global__ __launch_bounds__(256)
void entmax_p_kernel(float* __restrict__ out,
                     const float* __restrict__ Cw, const float* __restrict__ Fw,
                     const float* __restrict__ Sw)
{
    __shared__ float sm[16];
    int row = blockIdx.x, b = blockIdx.y, mat = blockIdx.z, tid = threadIdx.x;
    size_t LL = (size_t)Ln * Ln;
    float* base = out + ((size_t)((mat + 1) * Bn + b)) * LL + (size_t)row * Ln;
    const float* wp = (mat == 0) ? Cw : (mat == 1 ? Fw : Sw);
    float w = 2.0f / (1.0f + expf(-wp[0]));

    float z[8];
#pragma unroll
    for (int j = 0; j < 8; j++) z[j] = base[tid + 256 * j];

    float s = 0.f;
#pragma unroll
    for (int j = 0; j < 8; j++) s += z[j];
    s = blk_sum_256(s, sm);
    float mu = s * (1.0f / 2048.0f);

    float hw = 0.5f * w;
    float m = -3.4e38f;
#pragma unroll
    for (int j = 0; j < 8; j++) { z[j] = (z[j] - mu) * hw; m = fmaxf(m, z[j]); }
    m = blk_max_256(m, sm);
#pragma unroll
    for (int j = 0; j < 8; j++) z[j] -= m;

    float tau = entmax_tau_256(z, sm);
#pragma unroll
    for (int j = 0; j < 8; j++) {
        float d = fmaxf(z[j] - tau, 0.f);
        base[tid + 256 * j] = fminf(d * d, 1.0f - EPSV);
    }
}

// ---------------- column sums (two-phase) ----------------
__global__ __launch_bounds__(256)
void colsum_part_kernel(const float* __restrict__ out)
{
    int j = blockIdx.x * 256 + threadIdx.x;
    int b = blockIdx.y;
    int chunk = blockIdx.z & 7;
    int m = blockIdx.z >> 3;                      // 0 -> pC (slot 1), 1 -> pS (slot 3)
    size_t LL = (size_t)Ln * Ln;
    const float* base = out + ((size_t)((m ? 3 : 1) * Bn + b)) * LL + (size_t)chunk * 256 * Ln + j;
    float s = 0.f;
#pragma unroll 8
    for (int i = 0; i < 256; i++) s += base[(size_t)i * Ln];
    g_csp[(((m * Bn + b) * 8) + chunk) * Ln + j] = s;
}
__global__ __launch_bounds__(256)
void colsum_fin_kernel()
{
    int j = blockIdx.x * 256 + threadIdx.x;
    int slot = blockIdx.y;                        // 0..3 = (m*Bn+b)
    float s = 0.f;
#pragma unroll
    for (int c = 0; c < 8; c++) s += g_csp[(slot * 8 + c) * Ln + j];
    g_cs[slot * Ln + j] = rsqrtf(s + EPSV);
}

// ----- fused: col-scale + EPS affine + log-combine + diag mask + entmax(H) --
__global__ __launch_bounds__(256)
void finalize_kernel(float* __restrict__ out)
{
    __shared__ float sm[16];
    int row = blockIdx.x, b = blockIdx.y, tid = threadIdx.x;
    size_t LL = (size_t)Ln * Ln;
    float* pH = out + ((size_t)(0 * Bn + b)) * LL + (size_t)row * Ln;
    float* pC = out + ((size_t)(1 * Bn + b)) * LL + (size_t)row * Ln;
    float* pF = out + ((size_t)(2 * Bn + b)) * LL + (size_t)row * Ln;
    float* pS = out + ((size_t)(3 * Bn + b)) * LL + (size_t)row * Ln;
    const float Aa = 1.0f - 2.0f * EPSV;

    float h[8];
#pragma unroll
    for (int m = 0; m < 8; m++) {
        int j = tid + 256 * m;
        float csC = g_cs[(0 * Bn + b) * Ln + j];
        float csS = g_cs[(1 * Bn + b) * Ln + j];
        float c = fmaf(pC[j] * csC, Aa, EPSV);
        float f = fmaf(pF[j],       Aa, EPSV);
        float s = fmaf(pS[j] * csS, Aa, EPSV);
        pC[j] = c; pF[j] = f; pS[j] = s;
        float hh = logf(c * f * s) * (1.0f / 3.0f);   // == (log c + log f + log s)/3
        h[m] = (j == row) ? -1e9f : hh;
    }

    float m = -3.4e38f;
#pragma unroll
    for (int j = 0; j < 8; j++) { h[j] *= 0.5f; m = fmaxf(m, h[j]); }
    m = blk_max_256(m, sm);
#pragma unroll
    for (int j = 0; j < 8; j++) h[j] -= m;
    float tau = entmax_tau_256(h, sm);
#pragma unroll
    for (int j = 0; j < 8; j++) {
        float d = fmaxf(h[j] - tau, 0.f);
        pH[tid + 256 * j] = d * d;
    }
}

// ---------------- launch ----------------
extern "C" void kernel_launch(void* const* d_in, const int* in_sizes, int n_in,
                              void* d_out, int out_size)
{
    const float* x  = (const float*)d_in[0];   // [2,2048,768]
    const float* Wq = (const float*)d_in[1];   // [512,768]
    const float* Wk = (const float*)d_in[2];   // [512,768]
    const float* qg = (const float*)d_in[3];
    const float* qb = (const float*)d_in[4];
    const float* kg = (const float*)d_in[5];
    const float* kb = (const float*)d_in[6];
    const float* Cw = (const float*)d_in[7];
    const float* Fw = (const float*)d_in[8];
    const float* Sw = (const float*)d_in[9];
    float* out = (float*)d_out;                // [H, pC, pF, pS] each [2,2048,2048]

    float *q, *k, *G, *T;
    cudaGetSymbolAddress((void**)&q, g_q);
    cudaGetSymbolAddress((void**)&k, g_k);
    cudaGetSymbolAddress((void**)&G, g_G);
    cudaGetSymbolAddress((void**)&T, g_T);

    const size_t LL = (size_t)Ln * Ln, LD = (size_t)Ln * Dn, DD = (size_t)Dn * Dn;
    const int SMEM = 64 * 1024;   // 4 x [2][16][128] floats

    cudaFuncSetAttribute(mma128<false, true>,  cudaFuncAttributeMaxDynamicSharedMemorySize, SMEM);
    cudaFuncSetAttribute(mma128<true, false>,  cudaFuncAttributeMaxDynamicSharedMemorySize, SMEM);
    cudaFuncSetAttribute(mma128<false, false>, cudaFuncAttributeMaxDynamicSharedMemorySize, SMEM);

    // 1) projections: q_pre = x @ Wq^T, k_pre = x @ Wk^T   (M=4096, N=512, K=768)
    {
        GB gb{};
        gb.A[0] = x; gb.B[0] = Wq; gb.C[0] = q;
        gb.A[1] = x; gb.B[1] = Wk; gb.C[1] = k;
        mma128<false, true><<<dim3(Dn / 128, (Bn * Ln) / 128, 2), 256, SMEM>>>(gb, En, En, En, Dn);
    }

    // 2) LayerNorm + RoPE in place
    lnrope_kernel<<<dim3(Bn * Ln, 2), 128>>>(q, k, qg, qb, kg, kb);

    // 3) Gram matrices: G[d][e] = sum_l A[l,d] B[l,e]   (M=N=512, K=2048, TA)
    {
        GB gb{};
        for (int b = 0; b < 2; b++) {
            gb.A[0 + b] = k + b * LD; gb.B[0 + b] = k + b * LD; gb.C[0 + b] = G + (0 + b) * DD; // Gkk
            gb.A[2 + b] = k + b * LD; gb.B[2 + b] = q + b * LD; gb.C[2 + b] = G + (2 + b) * DD; // Gkq
            gb.A[4 + b] = q + b * LD; gb.B[4 + b] = q + b * LD; gb.C[4 + b] = G + (4 + b) * DD; // Gqq
        }
        mma128<true, false><<<dim3(Dn / 128, Dn / 128, 6), 256, SMEM>>>(gb, Ln, Dn, Dn, Dn);
    }

    // 4) T = U @ G   (M=2048, N=512, K=512)
    {
        GB gb{};
        for (int b = 0; b < 2; b++) {
            gb.A[0 + b] = q + b * LD; gb.B[0 + b] = G + (0 + b) * DD; gb.C[0 + b] = T + (0 + b) * LD; // Tc
            gb.A[2 + b] = q + b * LD; gb.B[2 + b] = G + (2 + b) * DD; gb.C[2 + b] = T + (2 + b) * LD; // Tf
            gb.A[4 + b] = k + b * LD; gb.B[4 + b] = G + (4 + b) * DD; gb.C[4 + b] = T + (4 + b) * LD; // Ts
        }
        mma128<false, false><<<dim3(Dn / 128, Ln / 128, 6), 256, SMEM>>>(gb, Dn, Dn, Dn, Dn);
    }

    // 5) raw = T @ V^T  -> out slots 1..3   (M=N=2048, K=512, TB)
    {
        GB gb{};
        for (int b = 0; b < 2; b++) {
            gb.A[0 + b] = T + (0 + b) * LD; gb.B[0 + b] = q + b * LD; gb.C[0 + b] = out + (size_t)(1 * Bn + b) * LL; // C_raw
            gb.A[2 + b] = T + (2 + b) * LD; gb.B[2 + b] = k + b * LD; gb.C[2 + b] = out + (size_t)(2 * Bn + b) * LL; // F_raw
            gb.A[4 + b] = T + (4 + b) * LD; gb.B[4 + b] = k + b * LD; gb.C[4 + b] = out + (size_t)(3 * Bn + b) * LL; // S_raw
        }
        mma128<false, true><<<dim3(Ln / 128, Ln / 128, 6), 256, SMEM>>>(gb, Dn, Dn, Dn, Ln);
    }

    // 6) entmax over raw rows, 7) column scales (2-phase), 8) finalize + H
    entmax_p_kernel<<<dim3(Ln, Bn, 3), 256>>>(out, Cw, Fw, Sw);
    colsum_part_kernel<<<dim3(Ln / 256, Bn, 16), 256>>>(out);
    colsum_fin_kernel<<<dim3(Ln / 256, 4), 256>>>();
    finalize_kernel<<<dim3(Ln, Bn), 256>>>(out);
}

// round 14
// speedup vs baseline: 1.3134x; 1.1882x over previous
#include <cuda_runtime.h>
#include <math.h>
#include <stdint.h>

// ---------------- problem constants ----------------
#define Bn 2
#define Ln 2048
#define Dn 512
#define En 768
#define EPSV 1e-6f

// ---------------- scratch (device globals; no allocation) ----------------
__device__ __align__(16) float g_q[Bn * Ln * Dn];      // 8 MB
__device__ __align__(16) float g_k[Bn * Ln * Dn];      // 8 MB
__device__ __align__(16) float g_G[6 * Dn * Dn];       // 6 MB  [Gkk0,Gkk1,Gkq0,Gkq1,Gqq0,Gqq1]
__device__ __align__(16) float g_T[6 * Ln * Dn];       // 24 MB [Tc0,Tc1,Tf0,Tf1,Ts0,Ts1]
__device__ __align__(16) float g_cs[4 * Ln];           // col scales [C b0, C b1, S b0, S b1]
__device__ __align__(16) float g_csp[4 * 8 * Ln];      // colsum partials

// ---------------- tf32 helpers ----------------
__device__ __forceinline__ float tf32r(float x) {
    uint32_t u;
    asm("cvt.rna.tf32.f32 %0, %1;" : "=r"(u) : "f"(x));
    return __uint_as_float(u);
}
__device__ __forceinline__ void mma_tf32(float* c, const uint32_t* a, const uint32_t* b) {
    asm volatile(
        "mma.sync.aligned.m16n8k8.row.col.f32.tf32.tf32.f32 "
        "{%0,%1,%2,%3}, {%4,%5,%6,%7}, {%8,%9}, {%0,%1,%2,%3};"
        : "+f"(c[0]), "+f"(c[1]), "+f"(c[2]), "+f"(c[3])
        : "r"(a[0]), "r"(a[1]), "r"(a[2]), "r"(a[3]), "r"(b[0]), "r"(b[1]));
}

// ------- batched 3xTF32 tensor-core GEMM, 128x128x16 tiles, fp32-grade -----
// C[M,N] = op(A)*op(B); TA: A stored [K,M] else [M,K]; TB: B stored [N,K] else [K,N].
// Each operand split hi/lo (hi=tf32(x), lo=tf32(x-hi));
// acc += Alo*Bhi + Ahi*Blo + Ahi*Bhi  -> effective precision ~2^-22 relative.
// SYM: C is square/symmetric; blockIdx.x enumerates lower-triangle tiles and
// off-diagonal tiles are mirror-written (C[j][i] = C[i][j]).
// smem semantic: tile[k][m] at physical column m ^ ((k&3)<<3) (conflict-free).
// Dynamic smem: 4 arrays x [2][16][128] floats = 64 KB. 2 CTAs/SM.
struct GB { const float* A[6]; const float* B[6]; float* C[6]; };

#define SMBUF 2048   // floats per [16][128] slice

template<bool TA, bool TB, bool SYM>
__global__ __launch_bounds__(256, 2)
void mma128(GB gb, int K, int lda, int ldb, int ldc)
{
    extern __shared__ float sm4[];
    float* AsH = sm4;            // [2][16][128]
    float* AsL = sm4 + 2 * SMBUF;
    float* BsH = sm4 + 4 * SMBUF;
    float* BsL = sm4 + 6 * SMBUF;

    const float* __restrict__ A  = gb.A[blockIdx.z];
    const float* __restrict__ Bm = gb.B[blockIdx.z];
    float* __restrict__ C        = gb.C[blockIdx.z];

    const int tid = threadIdx.x, lane = tid & 31, warp = tid >> 5;
    const int wm = (warp >> 2) * 64, wn = (warp & 3) * 32;   // warp tile 64x32

    int bm, bn;
    if (SYM) {
        int idx = blockIdx.x;                       // triangular index
        bm = (int)((sqrtf(8.0f * idx + 1.0f) - 1.0f) * 0.5f);
        while ((bm + 1) * (bm + 2) / 2 <= idx) bm++;
        while (bm * (bm + 1) / 2 > idx) bm--;
        bn = idx - bm * (bm + 1) / 2;
    } else {
        bm = blockIdx.y; bn = blockIdx.x;
    }
    const int m0 = bm * 128, n0 = bn * 128;

    float acc[4][4][4];
#pragma unroll
    for (int i = 0; i < 4; i++)
#pragma unroll
        for (int j = 0; j < 4; j++)
#pragma unroll
            for (int v = 0; v < 4; v++) acc[i][j][v] = 0.f;

    float4 ra[2], rb[2];

    auto ldgA = [&](int k0) {
        if (!TA) {
            int m = tid & 127, kq0 = tid >> 7;               // kq0 in {0,1}
#pragma unroll
            for (int p = 0; p < 2; p++) {
                int kq = kq0 + p * 2;                        // 0..3
                ra[p] = *(const float4*)(A + (size_t)(m0 + m) * lda + k0 + kq * 4);
            }
        } else {
#pragma unroll
            for (int p = 0; p < 2; p++) {
                int qi = tid + p * 256;
                int k = qi >> 5, m = (qi & 31) * 4;
                ra[p] = *(const float4*)(A + (size_t)(k0 + k) * lda + m0 + m);
            }
        }
    };
    auto ldgB = [&](int k0) {
        if (!TB) {
#pragma unroll
            for (int p = 0; p < 2; p++) {
                int qi = tid + p * 256;
                int k = qi >> 5, n = (qi & 31) * 4;
                rb[p] = *(const float4*)(Bm + (size_t)(k0 + k) * ldb + n0 + n);
            }
        } else {
            int n = tid & 127, kq0 = tid >> 7;
#pragma unroll
            for (int p = 0; p < 2; p++) {
                int kq = kq0 + p * 2;
                rb[p] = *(const float4*)(Bm + (size_t)(n0 + n) * ldb + k0 + kq * 4);
            }
        }
    };
    auto stsA = [&](int buf) {
        int base = buf * SMBUF;
        if (!TA) {
            int m = tid & 127, kq0 = tid >> 7;
#pragma unroll
            for (int p = 0; p < 2; p++) {
                int k = (kq0 + p * 2) * 4;
                float v[4] = {ra[p].x, ra[p].y, ra[p].z, ra[p].w};
#pragma unroll
                for (int j = 0; j < 4; j++) {
                    float hi = tf32r(v[j]);
                    int idx = base + (k + j) * 128 + (m ^ (j << 3));
                    AsH[idx] = hi;
                    AsL[idx] = tf32r(v[j] - hi);
                }
            }
        } else {
#pragma unroll
            for (int p = 0; p < 2; p++) {
                int qi = tid + p * 256;
                int k = qi >> 5, m = (qi & 31) * 4;
                float4 h = make_float4(tf32r(ra[p].x), tf32r(ra[p].y),
                                       tf32r(ra[p].z), tf32r(ra[p].w));
                float4 l = make_float4(tf32r(ra[p].x - h.x), tf32r(ra[p].y - h.y),
                                       tf32r(ra[p].z - h.z), tf32r(ra[p].w - h.w));
                int idx = base + k * 128 + (m ^ ((k & 3) << 3));
                *(float4*)&AsH[idx] = h;
                *(float4*)&AsL[idx] = l;
            }
        }
    };
    auto stsB = [&](int buf) {
        int base = buf * SMBUF;
        if (!TB) {
#pragma unroll
            for (int p = 0; p < 2; p++) {
                int qi = tid + p * 256;
                int k = qi >> 5, n = (qi & 31) * 4;
                float4 h = make_float4(tf32r(rb[p].x), tf32r(rb[p].y),
                                       tf32r(rb[p].z), tf32r(rb[p].w));
                float4 l = make_float4(tf32r(rb[p].x - h.x), tf32r(rb[p].y - h.y),
                                       tf32r(rb[p].z - h.z), tf32r(rb[p].w - h.w));
                int idx = base + k * 128 + (n ^ ((k & 3) << 3));
                *(float4*)&BsH[idx] = h;
                *(float4*)&BsL[idx] = l;
            }
        } else {
            int n = tid & 127, kq0 = tid >> 7;
#pragma unroll
            for (int p = 0; p < 2; p++) {
                int k = (kq0 + p * 2) * 4;
                float v[4] = {rb[p].x, rb[p].y, rb[p].z, rb[p].w};
#pragma unroll
                for (int j = 0; j < 4; j++) {
                    float hi = tf32r(v[j]);
                    int idx = base + (k + j) * 128 + (n ^ (j << 3));
                    BsH[idx] = hi;
                    BsL[idx] = tf32r(v[j] - hi);
                }
            }
        }
    };
    auto compute = [&](int buf) {
        const int base = buf * SMBUF;
        const int sw = (lane & 3) << 3;
#pragma unroll
        for (int kc = 0; kc < 2; kc++) {
            int c = kc * 8 + (lane & 3);
            int rowc0 = base + c * 128, rowc4 = base + (c + 4) * 128;
            uint32_t afh[4][4], afl[4][4];
#pragma unroll
            for (int i = 0; i < 4; i++) {
                int r = wm + i * 16 + (lane >> 2);
                int i00 = rowc0 + (r ^ sw), i01 = rowc0 + ((r + 8) ^ sw);
                int i10 = rowc4 + (r ^ sw), i11 = rowc4 + ((r + 8) ^ sw);
                afh[i][0] = __float_as_uint(AsH[i00]);
                afh[i][1] = __float_as_uint(AsH[i01]);
                afh[i][2] = __float_as_uint(AsH[i10]);
                afh[i][3] = __float_as_uint(AsH[i11]);
                afl[i][0] = __float_as_uint(AsL[i00]);
                afl[i][1] = __float_as_uint(AsL[i01]);
                afl[i][2] = __float_as_uint(AsL[i10]);
                afl[i][3] = __float_as_uint(AsL[i11]);
            }
#pragma unroll
            for (int j = 0; j < 4; j++) {
                int n = wn + j * 8 + (lane >> 2);
                uint32_t bh[2], bl[2];
                bh[0] = __float_as_uint(BsH[rowc0 + (n ^ sw)]);
                bh[1] = __float_as_uint(BsH[rowc4 + (n ^ sw)]);
                bl[0] = __float_as_uint(BsL[rowc0 + (n ^ sw)]);
                bl[1] = __float_as_uint(BsL[rowc4 + (n ^ sw)]);
#pragma unroll
                for (int i = 0; i < 4; i++) {
                    mma_tf32(acc[i][j], afl[i], bh);   // small terms first
                    mma_tf32(acc[i][j], afh[i], bl);
                    mma_tf32(acc[i][j], afh[i], bh);
                }
            }
        }
    };

    const int nt = K >> 4;
    ldgA(0); ldgB(0); stsA(0); stsB(0);
    __syncthreads();
#pragma unroll 1
    for (int t = 0; t < nt; t++) {
        int buf = t & 1;
        if (t + 1 < nt) { ldgA((t + 1) << 4); ldgB((t + 1) << 4); }
        compute(buf);
        if (t + 1 < nt) { stsA(buf ^ 1); stsB(buf ^ 1); __syncthreads(); }
    }

#pragma unroll
    for (int i = 0; i < 4; i++) {
        int r = m0 + wm + i * 16 + (lane >> 2);
#pragma unroll
        for (int j = 0; j < 4; j++) {
            int cN = n0 + wn + j * 8 + (lane & 3) * 2;
            *(float2*)&C[(size_t)r * ldc + cN]       = make_float2(acc[i][j][0], acc[i][j][1]);
            *(float2*)&C[(size_t)(r + 8) * ldc + cN] = make_float2(acc[i][j][2], acc[i][j][3]);
            if (SYM && bm != bn) {                      // mirror write C[j][i]
                C[(size_t)cN * ldc + r]           = acc[i][j][0];
                C[(size_t)(cN + 1) * ldc + r]     = acc[i][j][1];
                C[(size_t)cN * ldc + r + 8]       = acc[i][j][2];
                C[(size_t)(cN + 1) * ldc + r + 8] = acc[i][j][3];
            }
        }
    }
}

// ---------------- reductions (256-thread blocks, sm = 16 floats) -----------
__device__ __forceinline__ float warp_sum_f(float v) {
#pragma unroll
    for (int o = 16; o; o >>= 1) v += __shfl_xor_sync(0xffffffffu, v, o);
    return v;
}
__device__ __forceinline__ float blk_sum_256(float v, float* sm) {
    v = warp_sum_f(v);
    int w = threadIdx.x >> 5, l = threadIdx.x & 31;
    __syncthreads();
    if (l == 0) sm[w] = v;
    __syncthreads();
    float r = 0.f;
#pragma unroll
    for (int i = 0; i < 8; i++) r += sm[i];
    return r;
}
__device__ __forceinline__ float blk_max_256(float v, float* sm) {
#pragma unroll
    for (int o = 16; o; o >>= 1) v = fmaxf(v, __shfl_xor_sync(0xffffffffu, v, o));
    int w = threadIdx.x >> 5, l = threadIdx.x & 31;
    __syncthreads();
    if (l == 0) sm[w] = v;
    __syncthreads();
    float r = sm[0];
#pragma unroll
    for (int i = 1; i < 8; i++) r = fmaxf(r, sm[i]);
    return r;
}
__device__ __forceinline__ float2 blk_sum2_256(float2 v, float* sm) {
#pragma unroll
    for (int o = 16; o; o >>= 1) {
        v.x += __shfl_xor_sync(0xffffffffu, v.x, o);
        v.y += __shfl_xor_sync(0xffffffffu, v.y, o);
    }
    int w = threadIdx.x >> 5, l = threadIdx.x & 31;
    __syncthreads();
    if (l == 0) { sm[w] = v.x; sm[8 + w] = v.y; }
    __syncthreads();
    float2 r = make_float2(0.f, 0.f);
#pragma unroll
    for (int i = 0; i < 8; i++) { r.x += sm[i]; r.y += sm[8 + i]; }
    return r;
}

// Newton solve for 1.5-entmax threshold: sum(max(z - tau, 0)^2) = 1.
// z halved and max-subtracted (max(z) == 0, tau* in [-1, 0)). Convex decreasing;
// Newton from tau=-1 converges monotonically from the left.
__device__ float entmax_tau_256(const float z[8], float* sm) {
    float tau = -1.0f;
#pragma unroll 1
    for (int it = 0; it < 50; it++) {
        float2 s = make_float2(0.f, 0.f);
#pragma unroll
        for (int j = 0; j < 8; j++) {
            float d = fmaxf(z[j] - tau, 0.f);
            s.x += d; s.y += d * d;
        }
        s = blk_sum2_256(s, sm);
        if (s.x <= 0.f) break;
        float dt = (s.y - 1.0f) / (2.0f * s.x);
        tau += dt;
        if (dt <= 1e-8f) break;
    }
    return tau;
}

// ---------------- LayerNorm + RoPE (in place on g_q / g_k) ----------------
__global__ __launch_bounds__(128)
void lnrope_kernel(float* __restrict__ q, float* __restrict__ k,
                   const float* __restrict__ qg, const float* __restrict__ qb,
                   const float* __restrict__ kg, const float* __restrict__ kb)
{
    __shared__ float sred[4];
    int row = blockIdx.x;
    int t = row & (Ln - 1);
    float* base = (blockIdx.y ? k : q) + (size_t)row * Dn;
    const float* gamma = blockIdx.y ? kg : qg;
    const float* beta  = blockIdx.y ? kb : qb;
    int tid = threadIdx.x;

    float v0 = base[tid], v1 = base[tid + 128], v2 = base[tid + 256], v3 = base[tid + 384];
    float s = warp_sum_f(v0 + v1 + v2 + v3);
    if ((tid & 31) == 0) sred[tid >> 5] = s;
    __syncthreads();
    float mu = (sred[0] + sred[1] + sred[2] + sred[3]) * (1.0f / 512.0f);
    float d0 = v0 - mu, d1 = v1 - mu, d2 = v2 - mu, d3 = v3 - mu;
    float sq = warp_sum_f(d0*d0 + d1*d1 + d2*d2 + d3*d3);
    __syncthreads();
    if ((tid & 31) == 0) sred[tid >> 5] = sq;
    __syncthreads();
    float var = (sred[0] + sred[1] + sred[2] + sred[3]) * (1.0f / 512.0f);
    float rs = rsqrtf(var + 1e-5f);

    float n0 = d0 * rs * gamma[tid]       + beta[tid];
    float n1 = d1 * rs * gamma[tid + 128] + beta[tid + 128];
    float n2 = d2 * rs * gamma[tid + 256] + beta[tid + 256];
    float n3 = d3 * rs * gamma[tid + 384] + beta[tid + 384];

    const double lg = 9.210340371976184 / 256.0;   // log(10000)/256
    float inv0 = (float)exp(-(double)tid * lg);
    float inv1 = (float)exp(-(double)(tid + 128) * lg);
    float ft = (float)t;
    float a0 = ft * inv0, a1 = ft * inv1;
    float c0 = cosf(a0), s0 = sinf(a0);
    float c1 = cosf(a1), s1 = sinf(a1);
    base[tid]       = n0 * c0 - n2 * s0;
    base[tid + 256] = n2 * c0 + n0 * s0;
    base[tid + 128] = n1 * c1 - n3 * s1;
    base[tid + 384] = n3 * c1 + n1 * s1;
}

// ------- row-center + scale + entmax + clip (in place on out slots 1..3) ---
__global__ __launch_bounds__(256)
void entmax_p_kernel(float* __restrict__ out,
                     const float* __restrict__ Cw, const float* __restrict__ Fw,
                     const float* __restrict__ Sw)
{
    __shared__ float sm[16];
    int row = blockIdx.x, b = blockIdx.y, mat = blockIdx.z, tid = threadIdx.x;
    size_t LL = (size_t)Ln * Ln;
    float* base = out + ((size_t)((mat + 1) * Bn + b)) * LL + (size_t)row * Ln;
    const float* wp = (mat == 0) ? Cw : (mat == 1 ? Fw : Sw);
    float w = 2.0f / (1.0f + expf(-wp[0]));

    float z[8];
#pragma unroll
    for (int j = 0; j < 8; j++) z[j] = base[tid + 256 * j];

    float s = 0.f;
#pragma unroll
    for (int j = 0; j < 8; j++) s += z[j];
    s = blk_sum_256(s, sm);
    float mu = s * (1.0f / 2048.0f);

    float hw = 0.5f * w;
    float m = -3.4e38f;
#pragma unroll
    for (int j = 0; j < 8; j++) { z[j] = (z[j] - mu) * hw; m = fmaxf(m, z[j]); }
    m = blk_max_256(m, sm);
#pragma unroll
    for (int j = 0; j < 8; j++) z[j] -= m;

    float tau = entmax_tau_256(z, sm);
#pragma unroll
    for (int j = 0; j < 8; j++) {
        float d = fmaxf(z[j] - tau, 0.f);
        base[tid + 256 * j] = fminf(d * d, 1.0f - EPSV);
    }
}

// ---------------- column sums (two-phase) ----------------
__global__ __launch_bounds__(256)
void colsum_part_kernel(const float* __restrict__ out)
{
    int j = blockIdx.x * 256 + threadIdx.x;
    int b = blockIdx.y;
    int chunk = blockIdx.z & 7;
    int m = blockIdx.z >> 3;                      // 0 -> pC (slot 1), 1 -> pS (slot 3)
    size_t LL = (size_t)Ln * Ln;
    const float* base = out + ((size_t)((m ? 3 : 1) * Bn + b)) * LL + (size_t)chunk * 256 * Ln + j;
    float s = 0.f;
#pragma unroll 8
    for (int i = 0; i < 256; i++) s += base[(size_t)i * Ln];
    g_csp[(((m * Bn + b) * 8) + chunk) * Ln + j] = s;
}
__global__ __launch_bounds__(256)
void colsum_fin_kernel()
{
    int j = blockIdx.x * 256 + threadIdx.x;
    int slot = blockIdx.y;                        // 0..3 = (m*Bn+b)
    float s = 0.f;
#pragma unroll
    for (int c = 0; c < 8; c++) s += g_csp[(slot * 8 + c) * Ln + j];
    g_cs[slot * Ln + j] = rsqrtf(s + EPSV);
}

// ----- fused: col-scale + EPS affine + log-combine + diag mask + entmax(H) --
__global__ __launch_bounds__(256)
void finalize_kernel(float* __restrict__ out)
{
    __shared__ float sm[16];
    int row = blockIdx.x, b = blockIdx.y, tid = threadIdx.x;
    size_t LL = (size_t)Ln * Ln;
    float* pH = out + ((size_t)(0 * Bn + b)) * LL + (size_t)row * Ln;
    float* pC = out + ((size_t)(1 * Bn + b)) * LL + (size_t)row * Ln;
    float* pF = out + ((size_t)(2 * Bn + b)) * LL + (size_t)row * Ln;
    float* pS = out + ((size_t)(3 * Bn + b)) * LL + (size_t)row * Ln;
    const float Aa = 1.0f - 2.0f * EPSV;

    float h[8];
#pragma unroll
    for (int m = 0; m < 8; m++) {
        int j = tid + 256 * m;
        float csC = g_cs[(0 * Bn + b) * Ln + j];
        float csS = g_cs[(1 * Bn + b) * Ln + j];
        float c = fmaf(pC[j] * csC, Aa, EPSV);
        float f = fmaf(pF[j],       Aa, EPSV);
        float s = fmaf(pS[j] * csS, Aa, EPSV);
        pC[j] = c; pF[j] = f; pS[j] = s;
        float hh = logf(c * f * s) * (1.0f / 3.0f);   // == (log c + log f + log s)/3
        h[m] = (j == row) ? -1e9f : hh;
    }

    float m = -3.4e38f;
#pragma unroll
    for (int j = 0; j < 8; j++) { h[j] *= 0.5f; m = fmaxf(m, h[j]); }
    m = blk_max_256(m, sm);
#pragma unroll
    for (int j = 0; j < 8; j++) h[j] -= m;
    float tau = entmax_tau_256(h, sm);
#pragma unroll
    for (int j = 0; j < 8; j++) {
        float d = fmaxf(h[j] - tau, 0.f);
        pH[tid + 256 * j] = d * d;
    }
}

// ---------------- launch ----------------
extern "C" void kernel_launch(void* const* d_in, const int* in_sizes, int n_in,
                              void* d_out, int out_size)
{
    const float* x  = (const float*)d_in[0];   // [2,2048,768]
    const float* Wq = (const float*)d_in[1];   // [512,768]
    const float* Wk = (const float*)d_in[2];   // [512,768]
    const float* qg = (const float*)d_in[3];
    const float* qb = (const float*)d_in[4];
    const float* kg = (const float*)d_in[5];
    const float* kb = (const float*)d_in[6];
    const float* Cw = (const float*)d_in[7];
    const float* Fw = (const float*)d_in[8];
    const float* Sw = (const float*)d_in[9];
    float* out = (float*)d_out;                // [H, pC, pF, pS] each [2,2048,2048]

    float *q, *k, *G, *T;
    cudaGetSymbolAddress((void**)&q, g_q);
    cudaGetSymbolAddress((void**)&k, g_k);
    cudaGetSymbolAddress((void**)&G, g_G);
    cudaGetSymbolAddress((void**)&T, g_T);

    const size_t LL = (size_t)Ln * Ln, LD = (size_t)Ln * Dn, DD = (size_t)Dn * Dn;
    const int SMEM = 64 * 1024;   // 4 x [2][16][128] floats

    cudaFuncSetAttribute(mma128<false, true,  false>, cudaFuncAttributeMaxDynamicSharedMemorySize, SMEM);
    cudaFuncSetAttribute(mma128<true,  false, false>, cudaFuncAttributeMaxDynamicSharedMemorySize, SMEM);
    cudaFuncSetAttribute(mma128<false, false, false>, cudaFuncAttributeMaxDynamicSharedMemorySize, SMEM);
    cudaFuncSetAttribute(mma128<false, true,  true>,  cudaFuncAttributeMaxDynamicSharedMemorySize, SMEM);

    // 1) projections: q_pre = x @ Wq^T, k_pre = x @ Wk^T   (M=4096, N=512, K=768)
    {
        GB gb{};
        gb.A[0] = x; gb.B[0] = Wq; gb.C[0] = q;
        gb.A[1] = x; gb.B[1] = Wk; gb.C[1] = k;
        mma128<false, true, false><<<dim3(Dn / 128, (Bn * Ln) / 128, 2), 256, SMEM>>>(gb, En, En, En, Dn);
    }

    // 2) LayerNorm + RoPE in place
    lnrope_kernel<<<dim3(Bn * Ln, 2), 128>>>(q, k, qg, qb, kg, kb);

    // 3) Gram matrices: G[d][e] = sum_l A[l,d] B[l,e]   (M=N=512, K=2048, TA)
    {
        GB gb{};
        for (int b = 0; b < 2; b++) {
            gb.A[0 + b] = k + b * LD; gb.B[0 + b] = k + b * LD; gb.C[0 + b] = G + (0 + b) * DD; // Gkk
            gb.A[2 + b] = k + b * LD; gb.B[2 + b] = q + b * LD; gb.C[2 + b] = G + (2 + b) * DD; // Gkq
            gb.A[4 + b] = q + b * LD; gb.B[4 + b] = q + b * LD; gb.C[4 + b] = G + (4 + b) * DD; // Gqq
        }
        mma128<true, false, false><<<dim3(Dn / 128, Dn / 128, 6), 256, SMEM>>>(gb, Ln, Dn, Dn, Dn);
    }

    // 4) T = U @ G   (M=2048, N=512, K=512)
    {
        GB gb{};
        for (int b = 0; b < 2; b++) {
            gb.A[0 + b] = q + b * LD; gb.B[0 + b] = G + (0 + b) * DD; gb.C[0 + b] = T + (0 + b) * LD; // Tc
            gb.A[2 + b] = q + b * LD; gb.B[2 + b] = G + (2 + b) * DD; gb.C[2 + b] = T + (2 + b) * LD; // Tf
            gb.A[4 + b] = k + b * LD; gb.B[4 + b] = G + (4 + b) * DD; gb.C[4 + b] = T + (4 + b) * LD; // Ts
        }
        mma128<false, false, false><<<dim3(Dn / 128, Ln / 128, 6), 256, SMEM>>>(gb, Dn, Dn, Dn, Dn);
    }

    // 5a) symmetric raw: C_raw = Tc @ q^T, S_raw = Ts @ k^T (lower triangle + mirror)
    {
        GB gb{};
        for (int b = 0; b < 2; b++) {
            gb.A[0 + b] = T + (0 + b) * LD; gb.B[0 + b] = q + b * LD; gb.C[0 + b] = out + (size_t)(1 * Bn + b) * LL; // C_raw
            gb.A[2 + b] = T + (4 + b) * LD; gb.B[2 + b] = k + b * LD; gb.C[2 + b] = out + (size_t)(3 * Bn + b) * LL; // S_raw
        }
        const int NT = (Ln / 128) * (Ln / 128 + 1) / 2;   // 136 triangular tiles
        mma128<false, true, true><<<dim3(NT, 1, 4), 256, SMEM>>>(gb, Dn, Dn, Dn, Ln);
    }
    // 5b) F_raw = Tf @ k^T (full)
    {
        GB gb{};
        for (int b = 0; b < 2; b++) {
            gb.A[b] = T + (2 + b) * LD; gb.B[b] = k + b * LD; gb.C[b] = out + (size_t)(2 * Bn + b) * LL;
        }
        mma128<false, true, false><<<dim3(Ln / 128, Ln / 128, 2), 256, SMEM>>>(gb, Dn, Dn, Dn, Ln);
    }

    // 6) entmax over raw rows, 7) column scales (2-phase), 8) finalize + H
    entmax_p_kernel<<<dim3(Ln, Bn, 3), 256>>>(out, Cw, Fw, Sw);
    colsum_part_kernel<<<dim3(Ln / 256, Bn, 16), 256>>>(out);
    colsum_fin_kernel<<<dim3(Ln / 256, 4), 256>>>();
    finalize_kernel<<<dim3(Ln, Bn), 256>>>(out);
}

// round 15
// speedup vs baseline: 1.8322x; 1.3950x over previous
#include <cuda_runtime.h>
#include <cuda_fp16.h>
#include <math.h>
#include <stdint.h>

// ---------------- problem constants ----------------
#define Bn 2
#define Ln 2048
#define Dn 512
#define En 768
#define EPSV 1e-6f

// ---------------- scratch (device globals; no allocation) ----------------
__device__ __align__(16) float g_q[Bn * Ln * Dn];      // 8 MB
__device__ __align__(16) float g_k[Bn * Ln * Dn];      // 8 MB
__device__ __align__(16) float g_G[6 * Dn * Dn];       // 6 MB  [Gkk0,Gkk1,Gkq0,Gkq1,Gqq0,Gqq1]
__device__ __align__(16) float g_T[6 * Ln * Dn];       // 24 MB [Tc0,Tc1,Tf0,Tf1,Ts0,Ts1]
__device__ __align__(16) float g_cs[4 * Ln];           // col scales [C b0, C b1, S b0, S b1]
__device__ __align__(16) float g_csp[4 * 8 * Ln];      // colsum partials

// ---------------- fp16x2 split helpers ----------------
// split2: pack (e, o) = values at (k, k+1) into h0-pair word w0 and h1-pair
// word w1, where x = h0 + h1 exactly captures x to ~2^-22 relative.
__device__ __forceinline__ void split2(float e, float o, uint32_t& w0, uint32_t& w1) {
    asm("cvt.rn.f16x2.f32 %0, %1, %2;" : "=r"(w0) : "f"(o), "f"(e));   // lo = e
    __half2 h = *reinterpret_cast<__half2*>(&w0);
    float e1 = e - __low2float(h);
    float o1 = o - __high2float(h);
    asm("cvt.rn.f16x2.f32 %0, %1, %2;" : "=r"(w1) : "f"(o1), "f"(e1));
}
__device__ __forceinline__ void mma_f16(float* c, const uint32_t* a, const uint32_t* b) {
    asm volatile(
        "mma.sync.aligned.m16n8k16.row.col.f32.f16.f16.f32 "
        "{%0,%1,%2,%3}, {%4,%5,%6,%7}, {%8,%9}, {%0,%1,%2,%3};"
        : "+f"(c[0]), "+f"(c[1]), "+f"(c[2]), "+f"(c[3])
        : "r"(a[0]), "r"(a[1]), "r"(a[2]), "r"(a[3]), "r"(b[0]), "r"(b[1]));
}

// ------ batched fp16x2 (double-half) tensor GEMM, 128x128x16 tiles ---------
// C[M,N] = op(A)*op(B)*cscale; TA: A stored [K,M] else [M,K]; TB: B stored
// [N,K] else [K,N]. B is premultiplied by bscale before splitting (keeps tiny
// operands out of fp16-subnormal range); compensated by cscale at the store.
// Split: x = h0 + h1 (fp16 each); acc += a1*b0 + a0*b1 + a0*b0 via m16n8k16.
// Effective precision ~3*2^-22 relative (matches fp32-grade requirement).
// SYM: C square/symmetric; blockIdx.x enumerates lower-triangle tiles and
// off-diagonal tiles are mirror-written.
// smem: 4 planes (A0,A1,B0,B1) x 2 buffers x [8][128] u32 (half2 pairs along
// k) = 32 KB; word [k2][m] at physical column m ^ ((k2&3)<<3) (conflict-free).
struct GB { const float* A[6]; const float* B[6]; float* C[6]; };

template<bool TA, bool TB, bool SYM>
__global__ __launch_bounds__(256, 2)
void mma128(GB gb, int K, int lda, int ldb, int ldc, float bscale, float cscale)
{
    extern __shared__ uint32_t smu[];   // 8192 u32 = 32 KB
    // plane bases (u32 units): A0=0, A1=2048, B0=4096, B1=6144; buf stride 1024

    const float* __restrict__ A  = gb.A[blockIdx.z];
    const float* __restrict__ Bm = gb.B[blockIdx.z];
    float* __restrict__ C        = gb.C[blockIdx.z];

    const int tid = threadIdx.x, lane = tid & 31, warp = tid >> 5;
    const int wm = (warp >> 2) * 64, wn = (warp & 3) * 32;   // warp tile 64x32

    int bm, bn;
    if (SYM) {
        int idx = blockIdx.x;                       // triangular index
        bm = (int)((sqrtf(8.0f * idx + 1.0f) - 1.0f) * 0.5f);
        while ((bm + 1) * (bm + 2) / 2 <= idx) bm++;
        while (bm * (bm + 1) / 2 > idx) bm--;
        bn = idx - bm * (bm + 1) / 2;
    } else {
        bm = blockIdx.y; bn = blockIdx.x;
    }
    const int m0 = bm * 128, n0 = bn * 128;

    float acc[4][4][4];
#pragma unroll
    for (int i = 0; i < 4; i++)
#pragma unroll
        for (int j = 0; j < 4; j++)
#pragma unroll
            for (int v = 0; v < 4; v++) acc[i][j][v] = 0.f;

    float4 ra[2], rb[2];

    auto ldgA = [&](int k0) {
        if (!TA) {                                   // [M,K]: float4 along k
            int m = tid & 127, kq0 = tid >> 7;
#pragma unroll
            for (int p = 0; p < 2; p++) {
                int kq = kq0 + p * 2;
                ra[p] = *(const float4*)(A + (size_t)(m0 + m) * lda + k0 + kq * 4);
            }
        } else {                                     // [K,M]: rows k,k+1 x 4 m
            int k2 = tid >> 5, m4 = (tid & 31) * 4;
            ra[0] = *(const float4*)(A + (size_t)(k0 + 2 * k2)     * lda + m0 + m4);
            ra[1] = *(const float4*)(A + (size_t)(k0 + 2 * k2 + 1) * lda + m0 + m4);
        }
    };
    auto ldgB = [&](int k0) {
        if (TB) {                                    // [N,K]: float4 along k
            int n = tid & 127, kq0 = tid >> 7;
#pragma unroll
            for (int p = 0; p < 2; p++) {
                int kq = kq0 + p * 2;
                rb[p] = *(const float4*)(Bm + (size_t)(n0 + n) * ldb + k0 + kq * 4);
            }
        } else {                                     // [K,N]: rows k,k+1 x 4 n
            int k2 = tid >> 5, n4 = (tid & 31) * 4;
            rb[0] = *(const float4*)(Bm + (size_t)(k0 + 2 * k2)     * ldb + n0 + n4);
            rb[1] = *(const float4*)(Bm + (size_t)(k0 + 2 * k2 + 1) * ldb + n0 + n4);
        }
    };
    auto stsA = [&](int buf) {
        uint32_t* A0 = smu + buf * 1024;
        uint32_t* A1 = smu + 2048 + buf * 1024;
        if (!TA) {
            int m = tid & 127, kq0 = tid >> 7;
#pragma unroll
            for (int p = 0; p < 2; p++) {
                int kq = kq0 + p * 2;
                float v[4] = {ra[p].x, ra[p].y, ra[p].z, ra[p].w};
#pragma unroll
                for (int j = 0; j < 2; j++) {
                    int k2 = kq * 2 + j;
                    uint32_t w0, w1;
                    split2(v[2 * j], v[2 * j + 1], w0, w1);
                    int idx = k2 * 128 + (m ^ ((k2 & 3) << 3));
                    A0[idx] = w0; A1[idx] = w1;
                }
            }
        } else {
            int k2 = tid >> 5, m4 = (tid & 31) * 4;
            float e[4] = {ra[0].x, ra[0].y, ra[0].z, ra[0].w};
            float o[4] = {ra[1].x, ra[1].y, ra[1].z, ra[1].w};
            uint32_t w0[4], w1[4];
#pragma unroll
            for (int c = 0; c < 4; c++) split2(e[c], o[c], w0[c], w1[c]);
            int idx = k2 * 128 + (m4 ^ ((k2 & 3) << 3));
            *(uint4*)&A0[idx] = make_uint4(w0[0], w0[1], w0[2], w0[3]);
            *(uint4*)&A1[idx] = make_uint4(w1[0], w1[1], w1[2], w1[3]);
        }
    };
    auto stsB = [&](int buf) {
        uint32_t* B0 = smu + 4096 + buf * 1024;
        uint32_t* B1 = smu + 6144 + buf * 1024;
        if (TB) {
            int n = tid & 127, kq0 = tid >> 7;
#pragma unroll
            for (int p = 0; p < 2; p++) {
                int kq = kq0 + p * 2;
                float v[4] = {rb[p].x * bscale, rb[p].y * bscale,
                              rb[p].z * bscale, rb[p].w * bscale};
#pragma unroll
                for (int j = 0; j < 2; j++) {
                    int k2 = kq * 2 + j;
                    uint32_t w0, w1;
                    split2(v[2 * j], v[2 * j + 1], w0, w1);
                    int idx = k2 * 128 + (n ^ ((k2 & 3) << 3));
                    B0[idx] = w0; B1[idx] = w1;
                }
            }
        } else {
            int k2 = tid >> 5, n4 = (tid & 31) * 4;
            float e[4] = {rb[0].x * bscale, rb[0].y * bscale, rb[0].z * bscale, rb[0].w * bscale};
            float o[4] = {rb[1].x * bscale, rb[1].y * bscale, rb[1].z * bscale, rb[1].w * bscale};
            uint32_t w0[4], w1[4];
#pragma unroll
            for (int c = 0; c < 4; c++) split2(e[c], o[c], w0[c], w1[c]);
            int idx = k2 * 128 + (n4 ^ ((k2 & 3) << 3));
            *(uint4*)&B0[idx] = make_uint4(w0[0], w0[1], w0[2], w0[3]);
            *(uint4*)&B1[idx] = make_uint4(w1[0], w1[1], w1[2], w1[3]);
        }
    };
    auto compute = [&](int buf) {
        const uint32_t* A0 = smu + buf * 1024;
        const uint32_t* A1 = smu + 2048 + buf * 1024;
        const uint32_t* B0 = smu + 4096 + buf * 1024;
        const uint32_t* B1 = smu + 6144 + buf * 1024;
        const int kp = lane & 3, sw = kp << 3, g = lane >> 2;
        uint32_t a0f[4][4], a1f[4][4];
#pragma unroll
        for (int i = 0; i < 4; i++) {
            int r = wm + i * 16 + g;
            int i0 = kp * 128 + (r ^ sw);
            int i1 = kp * 128 + ((r + 8) ^ sw);
            int i2 = (kp + 4) * 128 + (r ^ sw);
            int i3 = (kp + 4) * 128 + ((r + 8) ^ sw);
            a0f[i][0] = A0[i0]; a0f[i][1] = A0[i1]; a0f[i][2] = A0[i2]; a0f[i][3] = A0[i3];
            a1f[i][0] = A1[i0]; a1f[i][1] = A1[i1]; a1f[i][2] = A1[i2]; a1f[i][3] = A1[i3];
        }
#pragma unroll
        for (int j = 0; j < 4; j++) {
            int n = wn + j * 8 + g;
            uint32_t b0[2], b1[2];
            b0[0] = B0[kp * 128 + (n ^ sw)];
            b0[1] = B0[(kp + 4) * 128 + (n ^ sw)];
            b1[0] = B1[kp * 128 + (n ^ sw)];
            b1[1] = B1[(kp + 4) * 128 + (n ^ sw)];
#pragma unroll
            for (int i = 0; i < 4; i++) {
                mma_f16(acc[i][j], a1f[i], b0);   // small terms first
                mma_f16(acc[i][j], a0f[i], b1);
                mma_f16(acc[i][j], a0f[i], b0);
            }
        }
    };

    const int nt = K >> 4;
    ldgA(0); ldgB(0); stsA(0); stsB(0);
    __syncthreads();
#pragma unroll 1
    for (int t = 0; t < nt; t++) {
        int buf = t & 1;
        if (t + 1 < nt) { ldgA((t + 1) << 4); ldgB((t + 1) << 4); }
        compute(buf);
        if (t + 1 < nt) { stsA(buf ^ 1); stsB(buf ^ 1); __syncthreads(); }
    }

#pragma unroll
    for (int i = 0; i < 4; i++) {
        int r = m0 + wm + i * 16 + (lane >> 2);
#pragma unroll
        for (int j = 0; j < 4; j++) {
            int cN = n0 + wn + j * 8 + (lane & 3) * 2;
            float v0 = acc[i][j][0] * cscale, v1 = acc[i][j][1] * cscale;
            float v2 = acc[i][j][2] * cscale, v3 = acc[i][j][3] * cscale;
            *(float2*)&C[(size_t)r * ldc + cN]       = make_float2(v0, v1);
            *(float2*)&C[(size_t)(r + 8) * ldc + cN] = make_float2(v2, v3);
            if (SYM && bm != bn) {                      // mirror write C[j][i]
                C[(size_t)cN * ldc + r]           = v0;
                C[(size_t)(cN + 1) * ldc + r]     = v1;
                C[(size_t)cN * ldc + r + 8]       = v2;
                C[(size_t)(cN + 1) * ldc + r + 8] = v3;
            }
        }
    }
}

// ---------------- reductions (256-thread blocks, sm = 16 floats) -----------
__device__ __forceinline__ float warp_sum_f(float v) {
#pragma unroll
    for (int o = 16; o; o >>= 1) v += __shfl_xor_sync(0xffffffffu, v, o);
    return v;
}
__device__ __forceinline__ float blk_sum_256(float v, float* sm) {
    v = warp_sum_f(v);
    int w = threadIdx.x >> 5, l = threadIdx.x & 31;
    __syncthreads();
    if (l == 0) sm[w] = v;
    __syncthreads();
    float r = 0.f;
#pragma unroll
    for (int i = 0; i < 8; i++) r += sm[i];
    return r;
}
__device__ __forceinline__ float blk_max_256(float v, float* sm) {
#pragma unroll
    for (int o = 16; o; o >>= 1) v = fmaxf(v, __shfl_xor_sync(0xffffffffu, v, o));
    int w = threadIdx.x >> 5, l = threadIdx.x & 31;
    __syncthreads();
    if (l == 0) sm[w] = v;
    __syncthreads();
    float r = sm[0];
#pragma unroll
    for (int i = 1; i < 8; i++) r = fmaxf(r, sm[i]);
    return r;
}
__device__ __forceinline__ float2 blk_sum2_256(float2 v, float* sm) {
#pragma unroll
    for (int o = 16; o; o >>= 1) {
        v.x += __shfl_xor_sync(0xffffffffu, v.x, o);
        v.y += __shfl_xor_sync(0xffffffffu, v.y, o);
    }
    int w = threadIdx.x >> 5, l = threadIdx.x & 31;
    __syncthreads();
    if (l == 0) { sm[w] = v.x; sm[8 + w] = v.y; }
    __syncthreads();
    float2 r = make_float2(0.f, 0.f);
#pragma unroll
    for (int i = 0; i < 8; i++) { r.x += sm[i]; r.y += sm[8 + i]; }
    return r;
}

// Newton solve for 1.5-entmax threshold: sum(max(z - tau, 0)^2) = 1.
// z halved and max-subtracted (max(z) == 0, tau* in [-1, 0)). Convex decreasing;
// Newton from tau=-1 converges monotonically from the left.
__device__ float entmax_tau_256(const float z[8], float* sm) {
    float tau = -1.0f;
#pragma unroll 1
    for (int it = 0; it < 50; it++) {
        float2 s = make_float2(0.f, 0.f);
#pragma unroll
        for (int j = 0; j < 8; j++) {
            float d = fmaxf(z[j] - tau, 0.f);
            s.x += d; s.y += d * d;
        }
        s = blk_sum2_256(s, sm);
        if (s.x <= 0.f) break;
        float dt = (s.y - 1.0f) / (2.0f * s.x);
        tau += dt;
        if (dt <= 1e-8f) break;
    }
    return tau;
}

// ---------------- LayerNorm + RoPE (in place on g_q / g_k) ----------------
__global__ __launch_bounds__(128)
void lnrope_kernel(float* __restrict__ q, float* __restrict__ k,
                   const float* __restrict__ qg, const float* __restrict__ qb,
                   const float* __restrict__ kg, const float* __restrict__ kb)
{
    __shared__ float sred[4];
    int row = blockIdx.x;
    int t = row & (Ln - 1);
    float* base = (blockIdx.y ? k : q) + (size_t)row * Dn;
    const float* gamma = blockIdx.y ? kg : qg;
    const float* beta  = blockIdx.y ? kb : qb;
    int tid = threadIdx.x;

    float v0 = base[tid], v1 = base[tid + 128], v2 = base[tid + 256], v3 = base[tid + 384];
    float s = warp_sum_f(v0 + v1 + v2 + v3);
    if ((tid & 31) == 0) sred[tid >> 5] = s;
    __syncthreads();
    float mu = (sred[0] + sred[1] + sred[2] + sred[3]) * (1.0f / 512.0f);
    float d0 = v0 - mu, d1 = v1 - mu, d2 = v2 - mu, d3 = v3 - mu;
    float sq = warp_sum_f(d0*d0 + d1*d1 + d2*d2 + d3*d3);
    __syncthreads();
    if ((tid & 31) == 0) sred[tid >> 5] = sq;
    __syncthreads();
    float var = (sred[0] + sred[1] + sred[2] + sred[3]) * (1.0f / 512.0f);
    float rs = rsqrtf(var + 1e-5f);

    float n0 = d0 * rs * gamma[tid]       + beta[tid];
    float n1 = d1 * rs * gamma[tid + 128] + beta[tid + 128];
    float n2 = d2 * rs * gamma[tid + 256] + beta[tid + 256];
    float n3 = d3 * rs * gamma[tid + 384] + beta[tid + 384];

    const double lg = 9.210340371976184 / 256.0;   // log(10000)/256
    float inv0 = (float)exp(-(double)tid * lg);
    float inv1 = (float)exp(-(double)(tid + 128) * lg);
    float ft = (float)t;
    float a0 = ft * inv0, a1 = ft * inv1;
    float c0 = cosf(a0), s0 = sinf(a0);
    float c1 = cosf(a1), s1 = sinf(a1);
    base[tid]       = n0 * c0 - n2 * s0;
    base[tid + 256] = n2 * c0 + n0 * s0;
    base[tid + 128] = n1 * c1 - n3 * s1;
    base[tid + 384] = n3 * c1 + n1 * s1;
}

// ------- row-center + scale + entmax + clip (in place on out slots 1..3) ---
__global__ __launch_bounds__(256)
void entmax_p_kernel(float* __restrict__ out,
                     const float* __restrict__ Cw, const float* __restrict__ Fw,
                     const float* __restrict__ Sw)
{
    __shared__ float sm[16];
    int row = blockIdx.x, b = blockIdx.y, mat = blockIdx.z, tid = threadIdx.x;
    size_t LL = (size_t)Ln * Ln;
    float* base = out + ((size_t)((mat + 1) * Bn + b)) * LL + (size_t)row * Ln;
    const float* wp = (mat == 0) ? Cw : (mat == 1 ? Fw : Sw);
    float w = 2.0f / (1.0f + expf(-wp[0]));

    float z[8];
#pragma unroll
    for (int j = 0; j < 8; j++) z[j] = base[tid + 256 * j];

    float s = 0.f;
#pragma unroll
    for (int j = 0; j < 8; j++) s += z[j];
    s = blk_sum_256(s, sm);
    float mu = s * (1.0f / 2048.0f);

    float hw = 0.5f * w;
    float m = -3.4e38f;
#pragma unroll
    for (int j = 0; j < 8; j++) { z[j] = (z[j] - mu) * hw; m = fmaxf(m, z[j]); }
    m = blk_max_256(m, sm);
#pragma unroll
    for (int j = 0; j < 8; j++) z[j] -= m;

    float tau = entmax_tau_256(z, sm);
#pragma unroll
    for (int j = 0; j < 8; j++) {
        float d = fmaxf(z[j] - tau, 0.f);
        base[tid + 256 * j] = fminf(d * d, 1.0f - EPSV);
    }
}

// ---------------- column sums (two-phase) ----------------
__global__ __launch_bounds__(256)
void colsum_part_kernel(const float* __restrict__ out)
{
    int j = blockIdx.x * 256 + threadIdx.x;
    int b = blockIdx.y;
    int chunk = blockIdx.z & 7;
    int m = blockIdx.z >> 3;                      // 0 -> pC (slot 1), 1 -> pS (slot 3)
    size_t LL = (size_t)Ln * Ln;
    const float* base = out + ((size_t)((m ? 3 : 1) * Bn + b)) * LL + (size_t)chunk * 256 * Ln + j;
    float s = 0.f;
#pragma unroll 8
    for (int i = 0; i < 256; i++) s += base[(size_t)i * Ln];
    g_csp[(((m * Bn + b) * 8) + chunk) * Ln + j] = s;
}
__global__ __launch_bounds__(256)
void colsum_fin_kernel()
{
    int j = blockIdx.x * 256 + threadIdx.x;
    int slot = blockIdx.y;                        // 0..3 = (m*Bn+b)
    float s = 0.f;
#pragma unroll
    for (int c = 0; c < 8; c++) s += g_csp[(slot * 8 + c) * Ln + j];
    g_cs[slot * Ln + j] = rsqrtf(s + EPSV);
}

// ----- fused: col-scale + EPS affine + log-combine + diag mask + entmax(H) --
__global__ __launch_bounds__(256)
void finalize_kernel(float* __restrict__ out)
{
    __shared__ float sm[16];
    int row = blockIdx.x, b = blockIdx.y, tid = threadIdx.x;
    size_t LL = (size_t)Ln * Ln;
    float* pH = out + ((size_t)(0 * Bn + b)) * LL + (size_t)row * Ln;
    float* pC = out + ((size_t)(1 * Bn + b)) * LL + (size_t)row * Ln;
    float* pF = out + ((size_t)(2 * Bn + b)) * LL + (size_t)row * Ln;
    float* pS = out + ((size_t)(3 * Bn + b)) * LL + (size_t)row * Ln;
    const float Aa = 1.0f - 2.0f * EPSV;

    float h[8];
#pragma unroll
    for (int m = 0; m < 8; m++) {
        int j = tid + 256 * m;
        float csC = g_cs[(0 * Bn + b) * Ln + j];
        float csS = g_cs[(1 * Bn + b) * Ln + j];
        float c = fmaf(pC[j] * csC, Aa, EPSV);
        float f = fmaf(pF[j],       Aa, EPSV);
        float s = fmaf(pS[j] * csS, Aa, EPSV);
        pC[j] = c; pF[j] = f; pS[j] = s;
        float hh = __logf(c * f * s) * (1.0f / 3.0f);   // == (log c + log f + log s)/3
        h[m] = (j == row) ? -1e9f : hh;
    }

    float m = -3.4e38f;
#pragma unroll
    for (int j = 0; j < 8; j++) { h[j] *= 0.5f; m = fmaxf(m, h[j]); }
    m = blk_max_256(m, sm);
#pragma unroll
    for (int j = 0; j < 8; j++) h[j] -= m;
    float tau = entmax_tau_256(h, sm);
#pragma unroll
    for (int j = 0; j < 8; j++) {
        float d = fmaxf(h[j] - tau, 0.f);
        pH[tid + 256 * j] = d * d;
    }
}

// ---------------- launch ----------------
extern "C" void kernel_launch(void* const* d_in, const int* in_sizes, int n_in,
                              void* d_out, int out_size)
{
    const float* x  = (const float*)d_in[0];   // [2,2048,768]
    const float* Wq = (const float*)d_in[1];   // [512,768]
    const float* Wk = (const float*)d_in[2];   // [512,768]
    const float* qg = (const float*)d_in[3];
    const float* qb = (const float*)d_in[4];
    const float* kg = (const float*)d_in[5];
    const float* kb = (const float*)d_in[6];
    const float* Cw = (const float*)d_in[7];
    const float* Fw = (const float*)d_in[8];
    const float* Sw = (const float*)d_in[9];
    float* out = (float*)d_out;                // [H, pC, pF, pS] each [2,2048,2048]

    float *q, *k, *G, *T;
    cudaGetSymbolAddress((void**)&q, g_q);
    cudaGetSymbolAddress((void**)&k, g_k);
    cudaGetSymbolAddress((void**)&G, g_G);
    cudaGetSymbolAddress((void**)&T, g_T);

    const size_t LL = (size_t)Ln * Ln, LD = (size_t)Ln * Dn, DD = (size_t)Dn * Dn;
    const int SMEM = 32 * 1024;   // 8192 u32

    // 1) projections: q_pre = x @ Wq^T, k_pre = x @ Wk^T   (M=4096, N=512, K=768)
    //    Wq entries ~0.036 -> h1 would be fp16-subnormal; bscale=32 keeps it normal.
    {
        GB gb{};
        gb.A[0] = x; gb.B[0] = Wq; gb.C[0] = q;
        gb.A[1] = x; gb.B[1] = Wk; gb.C[1] = k;
        mma128<false, true, false><<<dim3(Dn / 128, (Bn * Ln) / 128, 2), 256, SMEM>>>(
            gb, En, En, En, Dn, 32.0f, 1.0f / 32.0f);
    }

    // 2) LayerNorm + RoPE in place
    lnrope_kernel<<<dim3(Bn * Ln, 2), 128>>>(q, k, qg, qb, kg, kb);

    // 3) Gram matrices: G[d][e] = sum_l A[l,d] B[l,e]   (M=N=512, K=2048, TA)
    {
        GB gb{};
        for (int b = 0; b < 2; b++) {
            gb.A[0 + b] = k + b * LD; gb.B[0 + b] = k + b * LD; gb.C[0 + b] = G + (0 + b) * DD; // Gkk
            gb.A[2 + b] = k + b * LD; gb.B[2 + b] = q + b * LD; gb.C[2 + b] = G + (2 + b) * DD; // Gkq
            gb.A[4 + b] = q + b * LD; gb.B[4 + b] = q + b * LD; gb.C[4 + b] = G + (4 + b) * DD; // Gqq
        }
        mma128<true, false, false><<<dim3(Dn / 128, Dn / 128, 6), 256, SMEM>>>(
            gb, Ln, Dn, Dn, Dn, 1.0f, 1.0f);
    }

    // 4) T = U @ G   (M=2048, N=512, K=512)
    {
        GB gb{};
        for (int b = 0; b < 2; b++) {
            gb.A[0 + b] = q + b * LD; gb.B[0 + b] = G + (0 + b) * DD; gb.C[0 + b] = T + (0 + b) * LD; // Tc
            gb.A[2 + b] = q + b * LD; gb.B[2 + b] = G + (2 + b) * DD; gb.C[2 + b] = T + (2 + b) * LD; // Tf
            gb.A[4 + b] = k + b * LD; gb.B[4 + b] = G + (4 + b) * DD; gb.C[4 + b] = T + (4 + b) * LD; // Ts
        }
        mma128<false, false, false><<<dim3(Dn / 128, Ln / 128, 6), 256, SMEM>>>(
            gb, Dn, Dn, Dn, Dn, 1.0f, 1.0f);
    }

    // 5a) symmetric raw: C_raw = Tc @ q^T, S_raw = Ts @ k^T (lower triangle + mirror)
    {
        GB gb{};
        for (int b = 0; b < 2; b++) {
            gb.A[0 + b] = T + (0 + b) * LD; gb.B[0 + b] = q + b * LD; gb.C[0 + b] = out + (size_t)(1 * Bn + b) * LL; // C_raw
            gb.A[2 + b] = T + (4 + b) * LD; gb.B[2 + b] = k + b * LD; gb.C[2 + b] = out + (size_t)(3 * Bn + b) * LL; // S_raw
        }
        const int NT = (Ln / 128) * (Ln / 128 + 1) / 2;   // 136 triangular tiles
        mma128<false, true, true><<<dim3(NT, 1, 4), 256, SMEM>>>(
            gb, Dn, Dn, Dn, Ln, 1.0f, 1.0f);
    }
    // 5b) F_raw = Tf @ k^T (full)
    {
        GB gb{};
        for (int b = 0; b < 2; b++) {
            gb.A[b] = T + (2 + b) * LD; gb.B[b] = k + b * LD; gb.C[b] = out + (size_t)(2 * Bn + b) * LL;
        }
        mma128<false, true, false><<<dim3(Ln / 128, Ln / 128, 2), 256, SMEM>>>(
            gb, Dn, Dn, Dn, Ln, 1.0f, 1.0f);
    }

    // 6) entmax over raw rows, 7) column scales (2-phase), 8) finalize + H
    entmax_p_kernel<<<dim3(Ln, Bn, 3), 256>>>(out, Cw, Fw, Sw);
    colsum_part_kernel<<<dim3(Ln / 256, Bn, 16), 256>>>(out);
    colsum_fin_kernel<<<dim3(Ln / 256, 4), 256>>>();
    finalize_kernel<<<dim3(Ln, Bn), 256>>>(out);
}